// round 2
// baseline (speedup 1.0000x reference)
#include <cuda_runtime.h>
#include <math.h>

// Problem constants (fixed-shape dataset)
#define BB 2
#define SS 2048
#define HH 1024
#define NH 16
#define HD 64
#define MM (BB*SS)          // 4096
#define HHALF 512

// ---------------- scratch (static device globals; no allocation) ----------------
__device__ float g_Q  [ (size_t)MM*HH ];   // (b,h,s,d)
__device__ float g_KT [ (size_t)MM*HH ];   // (b,h,d,s)
__device__ float g_V  [ (size_t)MM*HH ];   // (b,h,s,d)
__device__ float g_ctx[ (size_t)MM*HH ];   // (b,s,h,d)
__device__ float g_hid[ (size_t)MM*HHALF ];
__device__ float g_dirw[(size_t)MM*NH ];   // 0.3*(gelu-mlp) per (b,s,h)

// ---------------- generic tiled fp32 GEMM: C = A(MxK) @ W(KxN) + bias ----------------
// mode 0: C[m*N+n]
// mode 1: head-perm  C[((b*16+h)*S+s)*64+d]   (Q, V)
// mode 2: head-perm-T C[((b*16+h)*64+d)*S+s]  (K^T)
__global__ __launch_bounds__(256) void gemm_bias_kernel(
    const float* __restrict__ A, const float* __restrict__ W,
    const float* __restrict__ bias, float* __restrict__ C,
    int M, int N, int K, int mode, int do_gelu, int S)
{
    __shared__ float As[16][68];   // [k][m], padded
    __shared__ float Ws[16][64];   // [k][n]

    const int tid = threadIdx.x;
    const int bm = blockIdx.y * 64;
    const int bn = blockIdx.x * 64;
    const int ty = tid >> 4;            // 0..15 -> rows ty*4..+3
    const int tx = tid & 15;            // 0..15 -> cols tx*4..+3

    const int ar = tid >> 2;            // 0..63
    const int ac = (tid & 3) * 4;       // 0,4,8,12
    const int wr = tid >> 4;            // 0..15
    const int wc = (tid & 15) * 4;

    float acc[4][4] = {};

    for (int kt = 0; kt < K; kt += 16) {
        float4 av = *(const float4*)&A[(size_t)(bm + ar) * K + kt + ac];
        As[ac + 0][ar] = av.x; As[ac + 1][ar] = av.y;
        As[ac + 2][ar] = av.z; As[ac + 3][ar] = av.w;
        *(float4*)&Ws[wr][wc] = *(const float4*)&W[(size_t)(kt + wr) * N + bn + wc];
        __syncthreads();
        #pragma unroll
        for (int kk = 0; kk < 16; kk++) {
            float4 a = *(const float4*)&As[kk][ty * 4];
            float4 b = *(const float4*)&Ws[kk][tx * 4];
            acc[0][0] += a.x * b.x; acc[0][1] += a.x * b.y; acc[0][2] += a.x * b.z; acc[0][3] += a.x * b.w;
            acc[1][0] += a.y * b.x; acc[1][1] += a.y * b.y; acc[1][2] += a.y * b.z; acc[1][3] += a.y * b.w;
            acc[2][0] += a.z * b.x; acc[2][1] += a.z * b.y; acc[2][2] += a.z * b.z; acc[2][3] += a.z * b.w;
            acc[3][0] += a.w * b.x; acc[3][1] += a.w * b.y; acc[3][2] += a.w * b.z; acc[3][3] += a.w * b.w;
        }
        __syncthreads();
    }

    #pragma unroll
    for (int i = 0; i < 4; i++) {
        #pragma unroll
        for (int j = 0; j < 4; j++) {
            int m = bm + ty * 4 + i;
            int n = bn + tx * 4 + j;
            float v = acc[i][j] + bias[n];
            if (do_gelu) v = 0.5f * v * (1.0f + erff(v * 0.70710678118654752f));
            if (mode == 0) {
                C[(size_t)m * N + n] = v;
            } else {
                int b = m / S, s = m - b * S;
                int h = n >> 6, d = n & 63;
                if (mode == 1) C[(((size_t)b * NH + h) * S + s) * HD + d] = v;
                else           C[(((size_t)b * NH + h) * HD + d) * S + s] = v;
            }
        }
    }
}

// ---------------- ds2: dirw = 0.3*(hid @ W(512x16) + b), hid = M x 512 ----------------
__global__ __launch_bounds__(256) void ds2_kernel(
    const float* __restrict__ hid, const float* __restrict__ W,
    const float* __restrict__ bias, float* __restrict__ out)
{
    __shared__ float sW[HHALF * NH];     // 32 KB
    __shared__ float sH[16][HHALF];      // 32 KB
    const int tid = threadIdx.x;
    const int row0 = blockIdx.x * 16;

    for (int i = tid; i < HHALF * NH; i += 256) sW[i] = W[i];
    for (int i = tid; i < 16 * HHALF; i += 256) {
        int r = i >> 9, c = i & (HHALF - 1);
        sH[r][c] = hid[(size_t)(row0 + r) * HHALF + c];
    }
    __syncthreads();

    const int r = tid >> 4;
    const int n = tid & 15;
    float acc = 0.0f;
    #pragma unroll 8
    for (int k = 0; k < HHALF; k++) acc += sH[r][k] * sW[k * NH + n];
    out[(size_t)(row0 + r) * NH + n] = 0.3f * (acc + bias[n]);
}

// ---------------- fused attention: scores -> +bias -> softmax -> (attn out, ctx) ----------------
// block: 256 threads, 16 queries of one (b,h). smem: sS[16][S] + sQT[64][16] + sB[8192]
__global__ __launch_bounds__(256, 1) void attn_kernel(
    const float* __restrict__ gQ, const float* __restrict__ gKT,
    const float* __restrict__ gV, const float* __restrict__ dirw,
    float* __restrict__ gAttn, float* __restrict__ gCtx,
    int S, int writeAttn)
{
    extern __shared__ float sm[];
    float* sS  = sm;                       // 16 * S
    float* sQT = sm + 16 * S;              // 64 * 16 (d-major Q)
    float* sB  = sQT + 64 * 16;            // 64*128 KT tile, reused as V tile [128][64]

    const int tid  = threadIdx.x;
    const int q0   = blockIdx.x * 16;
    const int h    = blockIdx.y;
    const int b    = blockIdx.z;
    const int bh   = b * NH + h;
    const size_t head = (size_t)bh * S * HD;

    // load Q tile transposed (d-major)
    for (int i = tid; i < 16 * HD; i += 256) {
        int r = i >> 6, c = i & 63;
        sQT[c * 16 + r] = gQ[head + (size_t)(q0 + r) * HD + c];
    }
    __syncthreads();

    const int warp = tid >> 5;       // 0..7 -> query pair (2w, 2w+1)
    const int lane = tid & 31;       // k quad = 4*lane

    const float bias0 = dirw[((size_t)b * S + q0 + 2 * warp    ) * NH + h];
    const float bias1 = dirw[((size_t)b * S + q0 + 2 * warp + 1) * NH + h];

    // ---- phase 1: scores ----
    for (int k0 = 0; k0 < S; k0 += 128) {
        for (int i4 = tid; i4 < 64 * 32; i4 += 256) {
            int d = i4 >> 5, c = (i4 & 31) * 4;
            *(float4*)&sB[d * 128 + c] =
                *(const float4*)&gKT[head + (size_t)d * S + k0 + c];
        }
        __syncthreads();

        float4 a0 = {0,0,0,0}, a1 = {0,0,0,0};
        #pragma unroll 8
        for (int d = 0; d < 64; d++) {
            float2 qv = *(const float2*)&sQT[d * 16 + 2 * warp];
            float4 bv = *(const float4*)&sB[d * 128 + 4 * lane];
            a0.x += qv.x * bv.x; a0.y += qv.x * bv.y; a0.z += qv.x * bv.z; a0.w += qv.x * bv.w;
            a1.x += qv.y * bv.x; a1.y += qv.y * bv.y; a1.z += qv.y * bv.z; a1.w += qv.y * bv.w;
        }
        float4 s0, s1;
        s0.x = a0.x * 0.125f + bias0; s0.y = a0.y * 0.125f + bias0;
        s0.z = a0.z * 0.125f + bias0; s0.w = a0.w * 0.125f + bias0;
        s1.x = a1.x * 0.125f + bias1; s1.y = a1.y * 0.125f + bias1;
        s1.z = a1.z * 0.125f + bias1; s1.w = a1.w * 0.125f + bias1;
        *(float4*)&sS[(size_t)(2 * warp    ) * S + k0 + 4 * lane] = s0;
        *(float4*)&sS[(size_t)(2 * warp + 1) * S + k0 + 4 * lane] = s1;
        __syncthreads();
    }

    // ---- phase 2: softmax per row (warp w owns rows 2w, 2w+1) ----
    const int n4 = S / 4;
    for (int rr = 0; rr < 2; rr++) {
        const int q = 2 * warp + rr;
        float4* row4 = (float4*)(sS + (size_t)q * S);
        float mx = -1e30f;
        for (int i = lane; i < n4; i += 32) {
            float4 v = row4[i];
            mx = fmaxf(mx, fmaxf(fmaxf(v.x, v.y), fmaxf(v.z, v.w)));
        }
        #pragma unroll
        for (int o = 16; o; o >>= 1) mx = fmaxf(mx, __shfl_xor_sync(~0u, mx, o));
        float sum = 0.0f;
        for (int i = lane; i < n4; i += 32) {
            float4 v = row4[i];
            v.x = expf(v.x - mx); v.y = expf(v.y - mx);
            v.z = expf(v.z - mx); v.w = expf(v.w - mx);
            sum += v.x + v.y + v.z + v.w;
            row4[i] = v;
        }
        #pragma unroll
        for (int o = 16; o; o >>= 1) sum += __shfl_xor_sync(~0u, sum, o);
        const float inv = 1.0f / sum;
        const size_t aBase = ((size_t)bh * S + (q0 + q)) * S;
        for (int i = lane; i < n4; i += 32) {
            float4 v = row4[i];
            v.x *= inv; v.y *= inv; v.z *= inv; v.w *= inv;
            row4[i] = v;
            if (writeAttn) *(float4*)&gAttn[aBase + 4 * i] = v;
        }
    }

    // ---- phase 3: ctx = attn @ V ----
    const int dx = (tid & 15) * 4;   // d quad
    const int qy = tid >> 4;         // query row
    float4 ctx = {0,0,0,0};
    for (int k0 = 0; k0 < S; k0 += 128) {
        __syncthreads();
        const float4* vsrc = (const float4*)(gV + head + (size_t)k0 * HD);
        float4* vdst = (float4*)sB;
        for (int i4 = tid; i4 < 128 * HD / 4; i4 += 256) vdst[i4] = vsrc[i4];
        __syncthreads();

        const float* arow = sS + (size_t)qy * S + k0;
        #pragma unroll 4
        for (int kk = 0; kk < 128; kk++) {
            float a = arow[kk];
            float4 v = *(const float4*)&sB[kk * HD + dx];
            ctx.x += a * v.x; ctx.y += a * v.y; ctx.z += a * v.z; ctx.w += a * v.w;
        }
    }
    // layout (b, s, h, d)
    size_t o = (((size_t)b * S + q0 + qy) * NH + h) * HD + dx;
    *(float4*)&g_ctx[o] = ctx;
    (void)gCtx;
}

// ---------------- host launcher ----------------
extern "C" void kernel_launch(void* const* d_in, const int* in_sizes, int n_in,
                              void* d_out, int out_size)
{
    const float* query  = (const float*)d_in[0];
    const float* key_in = (const float*)d_in[1];
    const float* value  = (const float*)d_in[2];
    // d_in[3] = direction_signal (int64) — unused by reference math
    const float* Wq_w = (const float*)d_in[4];
    const float* Wq_b = (const float*)d_in[5];
    const float* Wk_w = (const float*)d_in[6];
    const float* Wk_b = (const float*)d_in[7];
    const float* Wv_w = (const float*)d_in[8];
    const float* Wv_b = (const float*)d_in[9];
    const float* ds1_w = (const float*)d_in[10];
    const float* ds1_b = (const float*)d_in[11];
    const float* ds2_w = (const float*)d_in[12];
    const float* ds2_b = (const float*)d_in[13];
    const float* fo_w  = (const float*)d_in[14];
    const float* fo_b  = (const float*)d_in[15];

    float *pQ, *pKT, *pV, *pCtx, *pHid, *pDirw;
    cudaGetSymbolAddress((void**)&pQ,    g_Q);
    cudaGetSymbolAddress((void**)&pKT,   g_KT);
    cudaGetSymbolAddress((void**)&pV,    g_V);
    cudaGetSymbolAddress((void**)&pCtx,  g_ctx);
    cudaGetSymbolAddress((void**)&pHid,  g_hid);
    cudaGetSymbolAddress((void**)&pDirw, g_dirw);

    dim3 blk(256);

    // projections (Q,V head-perm; K head-perm transposed)
    gemm_bias_kernel<<<dim3(HH / 64, MM / 64), blk>>>(query,  Wq_w, Wq_b, pQ,  MM, HH, HH, 1, 0, SS);
    gemm_bias_kernel<<<dim3(HH / 64, MM / 64), blk>>>(key_in, Wk_w, Wk_b, pKT, MM, HH, HH, 2, 0, SS);
    gemm_bias_kernel<<<dim3(HH / 64, MM / 64), blk>>>(value,  Wv_w, Wv_b, pV,  MM, HH, HH, 1, 0, SS);

    // direction bias MLP: gelu(query @ ds1 + b1) @ ds2 + b2, scaled by 0.3
    gemm_bias_kernel<<<dim3(HHALF / 64, MM / 64), blk>>>(query, ds1_w, ds1_b, pHid, MM, HHALF, HH, 0, 1, SS);
    ds2_kernel<<<MM / 16, 256>>>(pHid, ds2_w, ds2_b, pDirw);

    // attention: write attn straight into d_out tail if it is part of the output
    const size_t outElems  = (size_t)MM * HH;
    const size_t attnElems = (size_t)BB * NH * SS * (size_t)SS;
    int writeAttn = ((size_t)out_size >= outElems + attnElems) ? 1 : 0;
    float* attnOut = writeAttn ? ((float*)d_out + outElems) : (float*)d_out;

    size_t smemBytes = (size_t)(16 * SS + 64 * 16 + 64 * 128) * sizeof(float); // 167936
    cudaFuncSetAttribute(attn_kernel, cudaFuncAttributeMaxDynamicSharedMemorySize, (int)smemBytes);
    attn_kernel<<<dim3(SS / 16, NH, BB), blk, smemBytes>>>(pQ, pKT, pV, pDirw, attnOut, pCtx, SS, writeAttn);

    // final projection
    gemm_bias_kernel<<<dim3(HH / 64, MM / 64), blk>>>(pCtx, fo_w, fo_b, (float*)d_out, MM, HH, HH, 0, 0, SS);
}

// round 3
// speedup vs baseline: 3.7592x; 3.7592x over previous
#include <cuda_runtime.h>
#include <math.h>
#include <stdint.h>

// ---------------- problem constants ----------------
#define BB 2
#define SEQ 2048
#define HH 1024
#define NH 16
#define HD 64
#define MM (BB*SEQ)          // 4096
#define HHALF 512

// ---------------- scratch ----------------
__device__ float g_Q  [(size_t)MM*HH];   // (b,h,s,d)
__device__ float g_KT [(size_t)MM*HH];   // (b,h,d,s)
__device__ float g_V  [(size_t)MM*HH];   // (b,h,s,d)
__device__ float g_ctx[(size_t)MM*HH];   // (b,s,h,d)
__device__ float g_hid[(size_t)MM*HHALF];
__device__ float g_dirw[(size_t)MM*NH];  // 0.3*(gelu-mlp) per (b,s,h)

// ---------------- tf32 mma helpers ----------------
__device__ __forceinline__ uint32_t f2tf(float x) {
    uint32_t r; asm("cvt.rna.tf32.f32 %0, %1;" : "=r"(r) : "f"(x)); return r;
}
__device__ __forceinline__ void mma8(float* c, const uint32_t* a, const uint32_t* b) {
    asm volatile(
        "mma.sync.aligned.m16n8k8.row.col.f32.tf32.tf32.f32 "
        "{%0,%1,%2,%3}, {%4,%5,%6,%7}, {%8,%9}, {%0,%1,%2,%3};"
        : "+f"(c[0]), "+f"(c[1]), "+f"(c[2]), "+f"(c[3])
        : "r"(a[0]), "r"(a[1]), "r"(a[2]), "r"(a[3]), "r"(b[0]), "r"(b[1]));
}
__device__ __forceinline__ void cpa16(uint32_t dst, const void* src) {
    asm volatile("cp.async.cg.shared.global [%0], [%1], 16;" :: "r"(dst), "l"(src));
}
#define CP_COMMIT() asm volatile("cp.async.commit_group;")
#define CP_WAIT(N)  asm volatile("cp.async.wait_group %0;" :: "n"(N))

// ---------------- TC GEMM: C = A(MxK) @ W(KxN) + bias ----------------
// mode 0: C[m*N+n] ; mode 1: C[((b*16+h)*S+s)*64+d] ; mode 2: C[((b*16+h)*64+d)*S+s]
#define GASTR 36    // A smem stride (mod32==4): a-frag banks 4*lr+lc -> conflict free
#define GWSTR 136   // W smem stride (mod32==8): b-frag banks 8*lc+lr -> conflict free
__global__ __launch_bounds__(256) void gemm_tc(
    const float* __restrict__ A, const float* __restrict__ W,
    const float* __restrict__ bias, float* __restrict__ C,
    int M, int N, int K, int mode, int do_gelu, int S)
{
    __shared__ float shA[2][128 * GASTR];
    __shared__ float shW[2][32 * GWSTR];

    const int tid = threadIdx.x, lane = tid & 31, wid = tid >> 5;
    const int warpM = wid & 3, warpN = wid >> 2;
    const int bm = blockIdx.y * 128, bn = blockIdx.x * 128;
    const int lr = lane >> 2, lc = lane & 3;

    const uint32_t sAaddr = (uint32_t)__cvta_generic_to_shared(&shA[0][0]);
    const uint32_t sWaddr = (uint32_t)__cvta_generic_to_shared(&shW[0][0]);

    const int ar = tid >> 3, ac = (tid & 7) * 4;
    const int wr = tid >> 5, wc = (tid & 31) * 4;

    auto loadA = [&](int buf, int kt) {
        #pragma unroll
        for (int i = 0; i < 4; i++) {
            int r = ar + 32 * i;
            cpa16(sAaddr + (uint32_t)(buf * 128 * GASTR + r * GASTR + ac) * 4,
                  &A[(size_t)(bm + r) * K + kt + ac]);
        }
    };
    auto loadW = [&](int buf, int kt) {
        #pragma unroll
        for (int i = 0; i < 4; i++) {
            int r = wr + 8 * i;
            cpa16(sWaddr + (uint32_t)(buf * 32 * GWSTR + r * GWSTR + wc) * 4,
                  &W[(size_t)(kt + r) * N + bn + wc]);
        }
    };

    float acc[2][8][4];
    #pragma unroll
    for (int i = 0; i < 2; i++)
        #pragma unroll
        for (int j = 0; j < 8; j++)
            #pragma unroll
            for (int k = 0; k < 4; k++) acc[i][j][k] = 0.0f;

    const int nk = K / 32;
    loadA(0, 0); loadW(0, 0); CP_COMMIT();
    if (nk > 1) { loadA(1, 32); loadW(1, 32); CP_COMMIT(); }

    for (int kt = 0; kt < nk; kt++) {
        if (kt + 1 < nk) { CP_WAIT(1); } else { CP_WAIT(0); }
        __syncthreads();
        const int buf = kt & 1;
        const float* a_b = &shA[buf][warpM * 32 * GASTR];
        const float* b_b = &shW[buf][warpN * 64];
        #pragma unroll
        for (int ks = 0; ks < 4; ks++) {
            const int k = ks * 8;
            uint32_t af[2][4];
            #pragma unroll
            for (int tm = 0; tm < 2; tm++) {
                const float* p = a_b + (tm * 16 + lr) * GASTR + k + lc;
                af[tm][0] = f2tf(p[0]);
                af[tm][1] = f2tf(p[8 * GASTR]);
                af[tm][2] = f2tf(p[4]);
                af[tm][3] = f2tf(p[8 * GASTR + 4]);
            }
            #pragma unroll
            for (int tn = 0; tn < 8; tn++) {
                uint32_t bf[2];
                const float* p = b_b + (k + lc) * GWSTR + tn * 8 + lr;
                bf[0] = f2tf(p[0]);
                bf[1] = f2tf(p[4 * GWSTR]);
                mma8(acc[0][tn], af[0], bf);
                mma8(acc[1][tn], af[1], bf);
            }
        }
        __syncthreads();
        if (kt + 2 < nk) { loadA(buf, (kt + 2) * 32); loadW(buf, (kt + 2) * 32); CP_COMMIT(); }
    }

    // epilogue
    #pragma unroll
    for (int tm = 0; tm < 2; tm++)
        #pragma unroll
        for (int tn = 0; tn < 8; tn++)
            #pragma unroll
            for (int i = 0; i < 4; i++) {
                int m = bm + warpM * 32 + tm * 16 + lr + ((i >= 2) ? 8 : 0);
                int n = bn + warpN * 64 + tn * 8 + lc * 2 + (i & 1);
                float v = acc[tm][tn][i] + bias[n];
                if (do_gelu) v = 0.5f * v * (1.0f + erff(v * 0.70710678118654752f));
                if (mode == 0) {
                    C[(size_t)m * N + n] = v;
                } else {
                    int b = m / S, s = m - b * S;
                    int h = n >> 6, d = n & 63;
                    if (mode == 1) C[(((size_t)b * NH + h) * S + s) * HD + d] = v;
                    else           C[(((size_t)b * NH + h) * HD + d) * S + s] = v;
                }
            }
}

// ---------------- ds2: dirw = 0.3*(hid @ W(512x16) + b) ----------------
__global__ __launch_bounds__(256) void ds2_kernel(
    const float* __restrict__ hid, const float* __restrict__ W,
    const float* __restrict__ bias, float* __restrict__ out)
{
    __shared__ float sW[HHALF * NH];
    __shared__ float sH[16][HHALF];
    const int tid = threadIdx.x;
    const int row0 = blockIdx.x * 16;

    for (int i = tid; i < HHALF * NH; i += 256) sW[i] = W[i];
    for (int i = tid; i < 16 * HHALF; i += 256) {
        int r = i >> 9, c = i & (HHALF - 1);
        sH[r][c] = hid[(size_t)(row0 + r) * HHALF + c];
    }
    __syncthreads();

    const int r = tid >> 4;
    const int n = tid & 15;
    float acc = 0.0f;
    #pragma unroll 8
    for (int k = 0; k < HHALF; k++) acc += sH[r][k] * sW[k * NH + n];
    out[(size_t)(row0 + r) * NH + n] = 0.3f * (acc + bias[n]);
}

// ---------------- fused TC attention ----------------
// block = 16 queries of one (b,h); 256 threads (8 warps).
// smem: sS[16][2052] scores, sQ[16][68], sKV double buffer (KT 64x136 / V 128x72)
#define SSTR  2052
#define KTSTR 136
#define VSTR  72
#define KVBUF 9216   // floats per buffer (>= 64*136=8704 and 128*72=9216)
__global__ __launch_bounds__(256, 1) void attn_tc(
    const float* __restrict__ gQ, const float* __restrict__ gKT,
    const float* __restrict__ gV, const float* __restrict__ dirw,
    float* __restrict__ gAttn, float* __restrict__ gCtx, int writeAttn)
{
    extern __shared__ float sm[];
    float* sS  = sm;                   // 16*2052
    float* sQ  = sm + 16 * SSTR;       // 16*68
    float* sKV = sQ + 16 * 68;         // 2*KVBUF

    const int tid = threadIdx.x, lane = tid & 31, wid = tid >> 5;
    const int lr = lane >> 2, lc = lane & 3;
    const int q0 = blockIdx.x * 16;
    const int h  = blockIdx.y, b = blockIdx.z;
    const size_t head = ((size_t)b * NH + h) * SEQ * HD;

    const uint32_t sQaddr  = (uint32_t)__cvta_generic_to_shared(sQ);
    const uint32_t sKVaddr = (uint32_t)__cvta_generic_to_shared(sKV);

    auto loadKT = [&](int buf, int k0) {   // 64 x 128 tile of gKT (d-major)
        #pragma unroll
        for (int i = 0; i < 8; i++) {
            int idx = tid + 256 * i;
            int d = idx >> 5, c = (idx & 31) * 4;
            cpa16(sKVaddr + (uint32_t)(buf * KVBUF + d * KTSTR + c) * 4,
                  &gKT[head + (size_t)d * SEQ + k0 + c]);
        }
    };
    auto loadV = [&](int buf, int k0) {    // 128 x 64 tile of gV (s-major)
        #pragma unroll
        for (int i = 0; i < 8; i++) {
            int idx = tid + 256 * i;
            int key = idx >> 4, c = (idx & 15) * 4;
            cpa16(sKVaddr + (uint32_t)(buf * KVBUF + key * VSTR + c) * 4,
                  &gV[head + (size_t)(k0 + key) * HD + c]);
        }
    };

    // prologue: Q tile + first two KT tiles
    {
        int r = tid >> 4, c = (tid & 15) * 4;
        cpa16(sQaddr + (uint32_t)(r * 68 + c) * 4, &gQ[head + (size_t)(q0 + r) * HD + c]);
    }
    loadKT(0, 0); CP_COMMIT();
    loadKT(1, 128); CP_COMMIT();
    CP_WAIT(1); __syncthreads();

    // hoist Q fragments (constant over all key tiles)
    uint32_t afr[8][4];
    #pragma unroll
    for (int ks = 0; ks < 8; ks++) {
        const float* p = sQ + lr * 68 + ks * 8 + lc;
        afr[ks][0] = f2tf(p[0]);
        afr[ks][1] = f2tf(p[8 * 68]);
        afr[ks][2] = f2tf(p[4]);
        afr[ks][3] = f2tf(p[8 * 68 + 4]);
    }
    const float bA = dirw[((size_t)b * SEQ + q0 + lr) * NH + h];
    const float bB = dirw[((size_t)b * SEQ + q0 + lr + 8) * NH + h];

    // ---- phase 1: scores = Q @ K^T * (1/8) + bias ----
    for (int t = 0; t < 16; t++) {
        const int buf = t & 1;
        const float* kb = sKV + buf * KVBUF + wid * 16 + lr;
        float acc[2][4] = {{0,0,0,0},{0,0,0,0}};
        #pragma unroll
        for (int ks = 0; ks < 8; ks++) {
            const int k = ks * 8;
            const float* p = kb + (k + lc) * KTSTR;
            uint32_t bf0[2], bf1[2];
            bf0[0] = f2tf(p[0]);              bf0[1] = f2tf(p[4 * KTSTR]);
            bf1[0] = f2tf(p[8]);              bf1[1] = f2tf(p[4 * KTSTR + 8]);
            mma8(acc[0], afr[ks], bf0);
            mma8(acc[1], afr[ks], bf1);
        }
        const int col0 = t * 128 + wid * 16;
        #pragma unroll
        for (int tn = 0; tn < 2; tn++) {
            float* s0 = sS + lr * SSTR + col0 + tn * 8 + lc * 2;
            s0[0] = acc[tn][0] * 0.125f + bA;
            s0[1] = acc[tn][1] * 0.125f + bA;
            s0[8 * SSTR]     = acc[tn][2] * 0.125f + bB;
            s0[8 * SSTR + 1] = acc[tn][3] * 0.125f + bB;
        }
        __syncthreads();                       // everyone done with buf before refill
        if (t + 2 < 16) { loadKT(buf, (t + 2) * 128); CP_COMMIT(); }
        if (t + 1 < 16) {
            if (t + 2 < 16) { CP_WAIT(1); } else { CP_WAIT(0); }
            __syncthreads();
        }
    }
    __syncthreads();

    // issue first V tiles so they overlap the softmax
    loadV(0, 0); CP_COMMIT();
    loadV(1, 128); CP_COMMIT();

    // ---- phase 2: softmax (warp w owns rows 2w, 2w+1) + attn output ----
    const int n4 = SEQ / 4;
    for (int rr = 0; rr < 2; rr++) {
        const int q = 2 * wid + rr;
        float4* row4 = (float4*)(sS + (size_t)q * SSTR);
        float mx = -1e30f;
        for (int i = lane; i < n4; i += 32) {
            float4 v = row4[i];
            mx = fmaxf(mx, fmaxf(fmaxf(v.x, v.y), fmaxf(v.z, v.w)));
        }
        #pragma unroll
        for (int o = 16; o; o >>= 1) mx = fmaxf(mx, __shfl_xor_sync(~0u, mx, o));
        float sum = 0.0f;
        for (int i = lane; i < n4; i += 32) {
            float4 v = row4[i];
            v.x = expf(v.x - mx); v.y = expf(v.y - mx);
            v.z = expf(v.z - mx); v.w = expf(v.w - mx);
            sum += v.x + v.y + v.z + v.w;
            row4[i] = v;
        }
        #pragma unroll
        for (int o = 16; o; o >>= 1) sum += __shfl_xor_sync(~0u, sum, o);
        const float inv = 1.0f / sum;
        const size_t aBase = (((size_t)b * NH + h) * SEQ + (q0 + q)) * SEQ;
        for (int i = lane; i < n4; i += 32) {
            float4 v = row4[i];
            v.x *= inv; v.y *= inv; v.z *= inv; v.w *= inv;
            row4[i] = v;
            if (writeAttn) *(float4*)&gAttn[aBase + 4 * i] = v;
        }
    }
    __syncthreads();

    // ---- phase 3: ctx = P @ V ----
    float acc[4] = {0, 0, 0, 0};
    for (int t = 0; t < 16; t++) {
        if (t + 1 < 16) { CP_WAIT(1); } else { CP_WAIT(0); }
        __syncthreads();
        const int buf = t & 1;
        const float* vb = sKV + buf * KVBUF + wid * 8 + lr;
        const float* prow = sS + lr * SSTR + t * 128 + lc;
        #pragma unroll
        for (int kk = 0; kk < 16; kk++) {
            const int k = kk * 8;
            uint32_t af[4];
            const float* p = prow + k;
            af[0] = f2tf(p[0]);
            af[1] = f2tf(p[8 * SSTR]);
            af[2] = f2tf(p[4]);
            af[3] = f2tf(p[8 * SSTR + 4]);
            uint32_t bf[2];
            const float* q = vb + (k + lc) * VSTR;
            bf[0] = f2tf(q[0]);
            bf[1] = f2tf(q[4 * VSTR]);
            mma8(acc, af, bf);
        }
        __syncthreads();
        if (t + 2 < 16) { loadV(buf, (t + 2) * 128); CP_COMMIT(); }
    }

    const int d0 = wid * 8 + lc * 2;
    size_t o0 = (((size_t)b * SEQ + q0 + lr) * NH + h) * HD + d0;
    gCtx[o0]     = acc[0];
    gCtx[o0 + 1] = acc[1];
    size_t o1 = (((size_t)b * SEQ + q0 + lr + 8) * NH + h) * HD + d0;
    gCtx[o1]     = acc[2];
    gCtx[o1 + 1] = acc[3];
}

// ---------------- host launcher ----------------
extern "C" void kernel_launch(void* const* d_in, const int* in_sizes, int n_in,
                              void* d_out, int out_size)
{
    const float* query  = (const float*)d_in[0];
    const float* key_in = (const float*)d_in[1];
    const float* value  = (const float*)d_in[2];
    // d_in[3] = direction_signal (unused by reference math)
    const float* Wq_w = (const float*)d_in[4];
    const float* Wq_b = (const float*)d_in[5];
    const float* Wk_w = (const float*)d_in[6];
    const float* Wk_b = (const float*)d_in[7];
    const float* Wv_w = (const float*)d_in[8];
    const float* Wv_b = (const float*)d_in[9];
    const float* ds1_w = (const float*)d_in[10];
    const float* ds1_b = (const float*)d_in[11];
    const float* ds2_w = (const float*)d_in[12];
    const float* ds2_b = (const float*)d_in[13];
    const float* fo_w  = (const float*)d_in[14];
    const float* fo_b  = (const float*)d_in[15];

    float *pQ, *pKT, *pV, *pCtx, *pHid, *pDirw;
    cudaGetSymbolAddress((void**)&pQ,    g_Q);
    cudaGetSymbolAddress((void**)&pKT,   g_KT);
    cudaGetSymbolAddress((void**)&pV,    g_V);
    cudaGetSymbolAddress((void**)&pCtx,  g_ctx);
    cudaGetSymbolAddress((void**)&pHid,  g_hid);
    cudaGetSymbolAddress((void**)&pDirw, g_dirw);

    dim3 blk(256);

    gemm_tc<<<dim3(HH / 128, MM / 128), blk>>>(query,  Wq_w, Wq_b, pQ,  MM, HH, HH, 1, 0, SEQ);
    gemm_tc<<<dim3(HH / 128, MM / 128), blk>>>(key_in, Wk_w, Wk_b, pKT, MM, HH, HH, 2, 0, SEQ);
    gemm_tc<<<dim3(HH / 128, MM / 128), blk>>>(value,  Wv_w, Wv_b, pV,  MM, HH, HH, 1, 0, SEQ);

    gemm_tc<<<dim3(HHALF / 128, MM / 128), blk>>>(query, ds1_w, ds1_b, pHid, MM, HHALF, HH, 0, 1, SEQ);
    ds2_kernel<<<MM / 16, 256>>>(pHid, ds2_w, ds2_b, pDirw);

    const size_t outElems  = (size_t)MM * HH;
    const size_t attnElems = (size_t)BB * NH * SEQ * (size_t)SEQ;
    int writeAttn = ((size_t)out_size >= outElems + attnElems) ? 1 : 0;
    float* attnOut = writeAttn ? ((float*)d_out + outElems) : (float*)d_out;

    size_t smemBytes = (size_t)(16 * SSTR + 16 * 68 + 2 * KVBUF) * sizeof(float); // 209408
    cudaFuncSetAttribute(attn_tc, cudaFuncAttributeMaxDynamicSharedMemorySize, (int)smemBytes);
    attn_tc<<<dim3(SEQ / 16, NH, BB), blk, smemBytes>>>(pQ, pKT, pV, pDirw, attnOut, pCtx, writeAttn);

    gemm_tc<<<dim3(HH / 128, MM / 128), blk>>>(pCtx, fo_w, fo_b, (float*)d_out, MM, HH, HH, 0, 0, SEQ);
}

// round 4
// speedup vs baseline: 4.1351x; 1.1000x over previous
#include <cuda_runtime.h>
#include <math.h>
#include <stdint.h>

// ---------------- problem constants ----------------
#define BB 2
#define SEQ 2048
#define HH 1024
#define NH 16
#define HD 64
#define MM (BB*SEQ)          // 4096
#define HHALF 512
#define LOG2E 1.4426950408889634f

// ---------------- scratch ----------------
__device__ float g_Q  [(size_t)MM*HH];   // (b,h,s,d)  tf32-rounded
__device__ float g_KT [(size_t)MM*HH];   // (b,h,d,s)  tf32-rounded
__device__ float g_V  [(size_t)MM*HH];   // (b,h,s,d)  tf32-rounded
__device__ float g_ctx[(size_t)MM*HH];   // (b,s,h,d)
__device__ float g_hid[(size_t)MM*HHALF];
__device__ float g_dirw[(size_t)MM*NH];  // 0.3*(gelu-mlp) per (b,s,h)

// ---------------- helpers ----------------
__device__ __forceinline__ uint32_t f2tf(float x) {
    uint32_t r; asm("cvt.rna.tf32.f32 %0, %1;" : "=r"(r) : "f"(x)); return r;
}
__device__ __forceinline__ float ex2f(float x) {
    float y; asm("ex2.approx.ftz.f32 %0, %1;" : "=f"(y) : "f"(x)); return y;
}
__device__ __forceinline__ void mma8(float* c, const uint32_t* a, const uint32_t* b) {
    asm volatile(
        "mma.sync.aligned.m16n8k8.row.col.f32.tf32.tf32.f32 "
        "{%0,%1,%2,%3}, {%4,%5,%6,%7}, {%8,%9}, {%0,%1,%2,%3};"
        : "+f"(c[0]), "+f"(c[1]), "+f"(c[2]), "+f"(c[3])
        : "r"(a[0]), "r"(a[1]), "r"(a[2]), "r"(a[3]), "r"(b[0]), "r"(b[1]));
}
__device__ __forceinline__ void cpa16(uint32_t dst, const void* src) {
    asm volatile("cp.async.cg.shared.global [%0], [%1], 16;" :: "r"(dst), "l"(src));
}
#define CP_COMMIT() asm volatile("cp.async.commit_group;")
#define CP_WAIT(N)  asm volatile("cp.async.wait_group %0;" :: "n"(N))

// ---------------- shared TC GEMM body: C = A(4096xK=1024) @ W(1024xN) + bias ----------------
#define GASTR 36
#define GWSTR 136
__device__ __forceinline__ void gemm_body(
    const float* __restrict__ A, const float* __restrict__ W,
    const float* __restrict__ bias, float* __restrict__ C,
    int N, int mode, int do_gelu, int round_out)
{
    __shared__ float shA[2][128 * GASTR];
    __shared__ float shW[2][32 * GWSTR];

    const int tid = threadIdx.x, lane = tid & 31, wid = tid >> 5;
    const int warpM = wid & 3, warpN = wid >> 2;
    const int bm = blockIdx.y * 128, bn = blockIdx.x * 128;
    const int lr = lane >> 2, lc = lane & 3;
    const int K = HH;

    const uint32_t sAaddr = (uint32_t)__cvta_generic_to_shared(&shA[0][0]);
    const uint32_t sWaddr = (uint32_t)__cvta_generic_to_shared(&shW[0][0]);

    const int ar = tid >> 3, ac = (tid & 7) * 4;
    const int wr = tid >> 5, wc = (tid & 31) * 4;

    auto loadA = [&](int buf, int kt) {
        #pragma unroll
        for (int i = 0; i < 4; i++) {
            int r = ar + 32 * i;
            cpa16(sAaddr + (uint32_t)(buf * 128 * GASTR + r * GASTR + ac) * 4,
                  &A[(size_t)(bm + r) * K + kt + ac]);
        }
    };
    auto loadW = [&](int buf, int kt) {
        #pragma unroll
        for (int i = 0; i < 4; i++) {
            int r = wr + 8 * i;
            cpa16(sWaddr + (uint32_t)(buf * 32 * GWSTR + r * GWSTR + wc) * 4,
                  &W[(size_t)(kt + r) * N + bn + wc]);
        }
    };

    float acc[2][8][4];
    #pragma unroll
    for (int i = 0; i < 2; i++)
        #pragma unroll
        for (int j = 0; j < 8; j++)
            #pragma unroll
            for (int k = 0; k < 4; k++) acc[i][j][k] = 0.0f;

    const int nk = K / 32;
    loadA(0, 0); loadW(0, 0); CP_COMMIT();
    loadA(1, 32); loadW(1, 32); CP_COMMIT();

    for (int kt = 0; kt < nk; kt++) {
        if (kt + 1 < nk) { CP_WAIT(1); } else { CP_WAIT(0); }
        __syncthreads();
        const int buf = kt & 1;
        const float* a_b = &shA[buf][warpM * 32 * GASTR];
        const float* b_b = &shW[buf][warpN * 64];
        #pragma unroll
        for (int ks = 0; ks < 4; ks++) {
            const int k = ks * 8;
            uint32_t af[2][4];
            #pragma unroll
            for (int tm = 0; tm < 2; tm++) {
                const float* p = a_b + (tm * 16 + lr) * GASTR + k + lc;
                af[tm][0] = f2tf(p[0]);
                af[tm][1] = f2tf(p[8 * GASTR]);
                af[tm][2] = f2tf(p[4]);
                af[tm][3] = f2tf(p[8 * GASTR + 4]);
            }
            #pragma unroll
            for (int tn = 0; tn < 8; tn++) {
                uint32_t bf[2];
                const float* p = b_b + (k + lc) * GWSTR + tn * 8 + lr;
                bf[0] = f2tf(p[0]);
                bf[1] = f2tf(p[4 * GWSTR]);
                mma8(acc[0][tn], af[0], bf);
                mma8(acc[1][tn], af[1], bf);
            }
        }
        __syncthreads();
        if (kt + 2 < nk) { loadA(buf, (kt + 2) * 32); loadW(buf, (kt + 2) * 32); CP_COMMIT(); }
    }

    #pragma unroll
    for (int tm = 0; tm < 2; tm++)
        #pragma unroll
        for (int tn = 0; tn < 8; tn++)
            #pragma unroll
            for (int i = 0; i < 4; i++) {
                int m = bm + warpM * 32 + tm * 16 + lr + ((i >= 2) ? 8 : 0);
                int n = bn + warpN * 64 + tn * 8 + lc * 2 + (i & 1);
                float v = acc[tm][tn][i] + bias[n];
                if (do_gelu) v = 0.5f * v * (1.0f + erff(v * 0.70710678118654752f));
                if (round_out) v = __uint_as_float(f2tf(v));
                if (mode == 0) {
                    C[(size_t)m * N + n] = v;
                } else {
                    int b = m / SEQ, s = m - b * SEQ;
                    int h = n >> 6, d = n & 63;
                    if (mode == 1) C[(((size_t)b * NH + h) * SEQ + s) * HD + d] = v;
                    else           C[(((size_t)b * NH + h) * HD + d) * SEQ + s] = v;
                }
            }
}

// ---------------- fused QKV + ds1 (z-indexed) ----------------
__global__ __launch_bounds__(256, 2) void mega_qkvd(
    const float* __restrict__ q, const float* __restrict__ k, const float* __restrict__ v,
    const float* __restrict__ Wq, const float* __restrict__ bq,
    const float* __restrict__ Wk, const float* __restrict__ bk,
    const float* __restrict__ Wv, const float* __restrict__ bv,
    const float* __restrict__ W1, const float* __restrict__ b1,
    float* pQ, float* pKT, float* pV, float* pHid)
{
    const int z = blockIdx.z;
    const float *A, *W, *bias; float* C; int N, mode, gelu, ro;
    if      (z == 0) { A = q; W = Wq; bias = bq; C = pQ;   N = HH;    mode = 1; gelu = 0; ro = 1; }
    else if (z == 1) { A = k; W = Wk; bias = bk; C = pKT;  N = HH;    mode = 2; gelu = 0; ro = 1; }
    else if (z == 2) { A = v; W = Wv; bias = bv; C = pV;   N = HH;    mode = 1; gelu = 0; ro = 1; }
    else             { A = q; W = W1; bias = b1; C = pHid; N = HHALF; mode = 0; gelu = 1; ro = 0; }
    if (blockIdx.x * 128 >= N) return;
    gemm_body(A, W, bias, C, N, mode, gelu, ro);
}

__global__ __launch_bounds__(256, 2) void gemm_fo(
    const float* __restrict__ A, const float* __restrict__ W,
    const float* __restrict__ bias, float* __restrict__ C)
{
    gemm_body(A, W, bias, C, HH, 0, 0, 0);
}

// ---------------- ds2: dirw = 0.3*(hid @ W(512x16) + b) ----------------
__global__ __launch_bounds__(512) void ds2_kernel(
    const float* __restrict__ hid, const float* __restrict__ W,
    const float* __restrict__ bias, float* __restrict__ out)
{
    __shared__ float sW[HHALF * NH];
    __shared__ float sH[16][HHALF];
    const int tid = threadIdx.x;
    const int row0 = blockIdx.x * 16;

    for (int i = tid; i < HHALF * NH; i += 512) sW[i] = W[i];
    for (int i = tid; i < 16 * HHALF; i += 512) {
        int r = i >> 9, c = i & (HHALF - 1);
        sH[r][c] = hid[(size_t)(row0 + r) * HHALF + c];
    }
    __syncthreads();

    const int r = tid >> 5, rem = tid & 31, n = rem >> 1, kh = rem & 1;
    float acc = 0.0f;
    const float* hrow = sH[r] + kh * 256;
    const float* wp = sW + kh * 256 * NH + n;
    #pragma unroll 8
    for (int k = 0; k < 256; k++) acc += hrow[k] * wp[k * NH];
    acc += __shfl_xor_sync(~0u, acc, 1);
    if (kh == 0) out[(size_t)(row0 + r) * NH + n] = 0.3f * (acc + bias[n]);
}

// ---------------- fused TC attention (512 threads, 16 queries/block) ----------------
#define SSTR  2052
#define KTSTR 136
#define VSTR  72
#define KVBUF 9216
#define SCL   (0.125f * LOG2E)
__global__ __launch_bounds__(512, 1) void attn_tc(
    const float* __restrict__ gQ, const float* __restrict__ gKT,
    const float* __restrict__ gV, const float* __restrict__ dirw,
    float* __restrict__ gAttn, float* __restrict__ gCtx, int writeAttn)
{
    extern __shared__ float sm[];
    float* sS   = sm;                      // 16*2052 scores (log2-domain), then P
    float* sQ   = sm + 16 * SSTR;          // 1088: Q tile, later reused for reductions
    float* sKV  = sQ + 1088;               // 2*KVBUF
    float* sRed = sKV + 2 * KVBUF;         // 16*68
    float* sPart   = sQ;                   // 256 (16 warps x 16 rows)
    float* sRowMax = sQ + 256;             // 16
    float* sInv    = sQ + 288;             // 16

    const int tid = threadIdx.x, lane = tid & 31, wid = tid >> 5;  // wid 0..15
    const int lr = lane >> 2, lc = lane & 3;
    const int q0 = blockIdx.x * 16;
    const int h = blockIdx.y, b = blockIdx.z;
    const size_t head = ((size_t)b * NH + h) * SEQ * HD;

    const uint32_t sQaddr  = (uint32_t)__cvta_generic_to_shared(sQ);
    const uint32_t sKVaddr = (uint32_t)__cvta_generic_to_shared(sKV);

    auto loadKT = [&](int buf, int k0) {   // 64 x 128 (d-major)
        #pragma unroll
        for (int i = 0; i < 4; i++) {
            int idx = tid + 512 * i;
            int d = idx >> 5, c = (idx & 31) * 4;
            cpa16(sKVaddr + (uint32_t)(buf * KVBUF + d * KTSTR + c) * 4,
                  &gKT[head + (size_t)d * SEQ + k0 + c]);
        }
    };
    auto loadV = [&](int buf, int k0) {    // 128 x 64 (s-major)
        #pragma unroll
        for (int i = 0; i < 4; i++) {
            int idx = tid + 512 * i;
            int key = idx >> 4, c = (idx & 15) * 4;
            cpa16(sKVaddr + (uint32_t)(buf * KVBUF + key * VSTR + c) * 4,
                  &gV[head + (size_t)(k0 + key) * HD + c]);
        }
    };

    // prologue: Q, then first two KT tiles
    if (tid < 256) {
        int r = tid >> 4, c = (tid & 15) * 4;
        cpa16(sQaddr + (uint32_t)(r * 68 + c) * 4, &gQ[head + (size_t)(q0 + r) * HD + c]);
    }
    CP_COMMIT();
    loadKT(0, 0); CP_COMMIT();
    loadKT(1, 128); CP_COMMIT();
    CP_WAIT(2); __syncthreads();   // Q resident

    // hoist Q fragments (pre-rounded tf32 -> raw bits)
    uint32_t afr[8][4];
    {
        const uint32_t* sQu = (const uint32_t*)sQ;
        #pragma unroll
        for (int ks = 0; ks < 8; ks++) {
            int base = lr * 68 + ks * 8 + lc;
            afr[ks][0] = sQu[base];
            afr[ks][1] = sQu[base + 8 * 68];
            afr[ks][2] = sQu[base + 4];
            afr[ks][3] = sQu[base + 8 * 68 + 4];
        }
    }
    const float bA2 = dirw[((size_t)b * SEQ + q0 + lr) * NH + h] * LOG2E;
    const float bB2 = dirw[((size_t)b * SEQ + q0 + lr + 8) * NH + h] * LOG2E;

    float mA = -1e30f, mB = -1e30f;

    // ---- phase 1: scores (log2-domain) + running row max ----
    for (int t = 0; t < 16; t++) {
        if (t < 15) { CP_WAIT(1); } else { CP_WAIT(0); }
        __syncthreads();
        const int buf = t & 1;
        const uint32_t* kbu = (const uint32_t*)(sKV + buf * KVBUF) + wid * 8 + lr;
        float acc[4] = {0, 0, 0, 0};
        #pragma unroll
        for (int ks = 0; ks < 8; ks++) {
            const uint32_t* p = kbu + (ks * 8 + lc) * KTSTR;
            uint32_t bf[2] = { p[0], p[4 * KTSTR] };
            mma8(acc, afr[ks], bf);
        }
        float v0 = acc[0] * SCL + bA2, v1 = acc[1] * SCL + bA2;
        float v2 = acc[2] * SCL + bB2, v3 = acc[3] * SCL + bB2;
        mA = fmaxf(mA, fmaxf(v0, v1));
        mB = fmaxf(mB, fmaxf(v2, v3));
        float* s0 = sS + lr * SSTR + t * 128 + wid * 8 + 2 * lc;
        *(float2*)s0 = make_float2(v0, v1);
        *(float2*)(s0 + 8 * SSTR) = make_float2(v2, v3);
        __syncthreads();
        if (t + 2 < 16) { loadKT(buf, (t + 2) * 128); CP_COMMIT(); }
    }

    // ---- row max reduce (quad shfl -> cross-warp smem) ----
    mA = fmaxf(mA, __shfl_xor_sync(~0u, mA, 1));
    mA = fmaxf(mA, __shfl_xor_sync(~0u, mA, 2));
    mB = fmaxf(mB, __shfl_xor_sync(~0u, mB, 1));
    mB = fmaxf(mB, __shfl_xor_sync(~0u, mB, 2));
    if (lc == 0) { sPart[wid * 16 + lr] = mA; sPart[wid * 16 + lr + 8] = mB; }

    // prefetch V (overlaps softmax)
    loadV(0, 0); CP_COMMIT();
    loadV(1, 128); CP_COMMIT();
    __syncthreads();
    if (tid < 16) {
        float m = sPart[tid];
        #pragma unroll
        for (int w = 1; w < 16; w++) m = fmaxf(m, sPart[w * 16 + tid]);
        sRowMax[tid] = m;
    }
    __syncthreads();

    // ---- exp sweep: warp w owns row w; P stored tf32-rounded, unnormalized ----
    {
        const float m = sRowMax[wid];
        float4* row4 = (float4*)(sS + (size_t)wid * SSTR);
        float sum = 0.0f;
        for (int i = lane; i < SEQ / 4; i += 32) {
            float4 v = row4[i];
            v.x = __uint_as_float(f2tf(ex2f(v.x - m)));
            v.y = __uint_as_float(f2tf(ex2f(v.y - m)));
            v.z = __uint_as_float(f2tf(ex2f(v.z - m)));
            v.w = __uint_as_float(f2tf(ex2f(v.w - m)));
            sum += v.x + v.y + v.z + v.w;
            row4[i] = v;
        }
        #pragma unroll
        for (int o = 16; o; o >>= 1) sum += __shfl_xor_sync(~0u, sum, o);
        if (lane == 0) sInv[wid] = 1.0f / sum;
    }
    __syncthreads();

    // ---- phase 3: ctx = P @ V, split-k across warp halves ----
    const int khalf = wid >> 3, c8 = (wid & 7) * 8;
    float acc[4] = {0, 0, 0, 0};
    for (int t = 0; t < 16; t++) {
        if (t < 15) { CP_WAIT(1); } else { CP_WAIT(0); }
        __syncthreads();
        const int buf = t & 1;
        const uint32_t* vbu = (const uint32_t*)(sKV + buf * KVBUF) + c8 + lr;
        const uint32_t* prow = (const uint32_t*)sS + lr * SSTR + t * 128 + khalf * 64 + lc;
        #pragma unroll
        for (int kk = 0; kk < 8; kk++) {
            const int k = kk * 8;
            uint32_t af[4] = { prow[k], prow[k + 8 * SSTR], prow[k + 4], prow[k + 4 + 8 * SSTR] };
            const uint32_t* qv = vbu + (khalf * 64 + k + lc) * VSTR;
            uint32_t bf[2] = { qv[0], qv[4 * VSTR] };
            mma8(acc, af, bf);
        }
        __syncthreads();
        if (t + 2 < 16) { loadV(buf, (t + 2) * 128); CP_COMMIT(); }
    }

    if (khalf == 1) {
        float* r = sRed + lr * 68 + c8 + 2 * lc;
        *(float2*)r = make_float2(acc[0], acc[1]);
        *(float2*)(r + 8 * 68) = make_float2(acc[2], acc[3]);
    }
    __syncthreads();
    if (khalf == 0) {
        const float invA = sInv[lr], invB = sInv[lr + 8];
        const float* r = sRed + lr * 68 + c8 + 2 * lc;
        float2 pA = *(const float2*)r, pB = *(const float2*)(r + 8 * 68);
        float2 oA = make_float2((acc[0] + pA.x) * invA, (acc[1] + pA.y) * invA);
        float2 oB = make_float2((acc[2] + pB.x) * invB, (acc[3] + pB.y) * invB);
        *(float2*)&gCtx[(((size_t)b * SEQ + q0 + lr)     * NH + h) * HD + c8 + 2 * lc] = oA;
        *(float2*)&gCtx[(((size_t)b * SEQ + q0 + lr + 8) * NH + h) * HD + c8 + 2 * lc] = oB;
    }

    // ---- attention output: normalize on the fly ----
    if (writeAttn) {
        const float inv = sInv[wid];
        const float4* row4 = (const float4*)(sS + (size_t)wid * SSTR);
        float4* dst = (float4*)(gAttn + (((size_t)b * NH + h) * SEQ + (q0 + wid)) * SEQ);
        for (int i = lane; i < SEQ / 4; i += 32) {
            float4 v = row4[i];
            v.x *= inv; v.y *= inv; v.z *= inv; v.w *= inv;
            dst[i] = v;
        }
    }
}

// ---------------- host launcher ----------------
extern "C" void kernel_launch(void* const* d_in, const int* in_sizes, int n_in,
                              void* d_out, int out_size)
{
    const float* query  = (const float*)d_in[0];
    const float* key_in = (const float*)d_in[1];
    const float* value  = (const float*)d_in[2];
    // d_in[3] = direction_signal (unused by reference math)
    const float* Wq_w = (const float*)d_in[4];
    const float* Wq_b = (const float*)d_in[5];
    const float* Wk_w = (const float*)d_in[6];
    const float* Wk_b = (const float*)d_in[7];
    const float* Wv_w = (const float*)d_in[8];
    const float* Wv_b = (const float*)d_in[9];
    const float* ds1_w = (const float*)d_in[10];
    const float* ds1_b = (const float*)d_in[11];
    const float* ds2_w = (const float*)d_in[12];
    const float* ds2_b = (const float*)d_in[13];
    const float* fo_w  = (const float*)d_in[14];
    const float* fo_b  = (const float*)d_in[15];

    float *pQ, *pKT, *pV, *pCtx, *pHid, *pDirw;
    cudaGetSymbolAddress((void**)&pQ,    g_Q);
    cudaGetSymbolAddress((void**)&pKT,   g_KT);
    cudaGetSymbolAddress((void**)&pV,    g_V);
    cudaGetSymbolAddress((void**)&pCtx,  g_ctx);
    cudaGetSymbolAddress((void**)&pHid,  g_hid);
    cudaGetSymbolAddress((void**)&pDirw, g_dirw);

    // QKV + ds1 in one launch
    mega_qkvd<<<dim3(HH / 128, MM / 128, 4), 256>>>(
        query, key_in, value, Wq_w, Wq_b, Wk_w, Wk_b, Wv_w, Wv_b,
        ds1_w, ds1_b, pQ, pKT, pV, pHid);

    ds2_kernel<<<MM / 16, 512>>>(pHid, ds2_w, ds2_b, pDirw);

    const size_t outElems  = (size_t)MM * HH;
    const size_t attnElems = (size_t)BB * NH * SEQ * (size_t)SEQ;
    int writeAttn = ((size_t)out_size >= outElems + attnElems) ? 1 : 0;
    float* attnOut = writeAttn ? ((float*)d_out + outElems) : (float*)d_out;

    size_t smemBytes = (size_t)(16 * SSTR + 1088 + 2 * KVBUF + 1088) * sizeof(float); // 213760
    cudaFuncSetAttribute(attn_tc, cudaFuncAttributeMaxDynamicSharedMemorySize, (int)smemBytes);
    attn_tc<<<dim3(SEQ / 16, NH, BB), 512, smemBytes>>>(pQ, pKT, pV, pDirw, attnOut, pCtx, writeAttn);

    gemm_fo<<<dim3(HH / 128, MM / 128), 256>>>(pCtx, fo_w, fo_b, (float*)d_out);
}

// round 5
// speedup vs baseline: 4.9134x; 1.1882x over previous
#include <cuda_runtime.h>
#include <math.h>
#include <stdint.h>

// ---------------- problem constants ----------------
#define BB 2
#define SEQ 2048
#define HH 1024
#define NH 16
#define HD 64
#define MM (BB*SEQ)          // 4096
#define HHALF 512
#define LOG2E 1.4426950408889634f

// ---------------- scratch ----------------
__device__ float g_Q  [(size_t)MM*HH];   // (b,h,s,d)  tf32-rounded
__device__ float g_KT [(size_t)MM*HH];   // (b,h,d,s)  tf32-rounded
__device__ float g_V  [(size_t)MM*HH];   // (b,h,s,d)  tf32-rounded
__device__ float g_ctx[(size_t)MM*HH];   // (b,s,h,d)  tf32-rounded
__device__ float g_hid[(size_t)MM*HHALF];
__device__ float g_dirw[(size_t)MM*NH];
// pre-rounded (tf32) copies of inputs & weights
__device__ float g_rq [(size_t)MM*HH];
__device__ float g_rk [(size_t)MM*HH];
__device__ float g_rv [(size_t)MM*HH];
__device__ float g_rwq[(size_t)HH*HH];
__device__ float g_rwk[(size_t)HH*HH];
__device__ float g_rwv[(size_t)HH*HH];
__device__ float g_rwo[(size_t)HH*HH];
__device__ float g_rw1[(size_t)HH*HHALF];
// fallback P storage when attention is not part of d_out
__device__ float g_P  [(size_t)BB*NH*SEQ*(size_t)SEQ];

// ---------------- helpers ----------------
__device__ __forceinline__ uint32_t f2tf(float x) {
    uint32_t r; asm("cvt.rna.tf32.f32 %0, %1;" : "=r"(r) : "f"(x)); return r;
}
__device__ __forceinline__ float ex2f(float x) {
    float y; asm("ex2.approx.ftz.f32 %0, %1;" : "=f"(y) : "f"(x)); return y;
}
__device__ __forceinline__ void mma8(float* c, const uint32_t* a, const uint32_t* b) {
    asm volatile(
        "mma.sync.aligned.m16n8k8.row.col.f32.tf32.tf32.f32 "
        "{%0,%1,%2,%3}, {%4,%5,%6,%7}, {%8,%9}, {%0,%1,%2,%3};"
        : "+f"(c[0]), "+f"(c[1]), "+f"(c[2]), "+f"(c[3])
        : "r"(a[0]), "r"(a[1]), "r"(a[2]), "r"(a[3]), "r"(b[0]), "r"(b[1]));
}
__device__ __forceinline__ void cpa16(uint32_t dst, const void* src) {
    asm volatile("cp.async.cg.shared.global [%0], [%1], 16;" :: "r"(dst), "l"(src));
}
#define CP_COMMIT() asm volatile("cp.async.commit_group;")
#define CP_WAIT(N)  asm volatile("cp.async.wait_group %0;" :: "n"(N))

// ---------------- preround: tf32-round inputs + weights ----------------
__global__ __launch_bounds__(256) void preround8(
    const float* s0, float* d0, int n0, const float* s1, float* d1, int n1,
    const float* s2, float* d2, int n2, const float* s3, float* d3, int n3,
    const float* s4, float* d4, int n4, const float* s5, float* d5, int n5,
    const float* s6, float* d6, int n6, const float* s7, float* d7, int n7)
{
    const float* srcs[8] = {s0,s1,s2,s3,s4,s5,s6,s7};
    float*       dsts[8] = {d0,d1,d2,d3,d4,d5,d6,d7};
    int          ns[8]   = {n0,n1,n2,n3,n4,n5,n6,n7};
    const int stride = gridDim.x * blockDim.x;
    const int t0 = blockIdx.x * blockDim.x + threadIdx.x;
    for (int t = 0; t < 8; t++) {
        const float4* src = (const float4*)srcs[t];
        float4* dst = (float4*)dsts[t];
        const int nq = ns[t] >> 2;
        for (int i = t0; i < nq; i += stride) {
            float4 v = src[i];
            v.x = __uint_as_float(f2tf(v.x)); v.y = __uint_as_float(f2tf(v.y));
            v.z = __uint_as_float(f2tf(v.z)); v.w = __uint_as_float(f2tf(v.w));
            dst[i] = v;
        }
    }
}

// ---------------- shared TC GEMM body (raw tf32 operands, no CVT) ----------------
#define GASTR 36
#define GWSTR 136
__device__ __forceinline__ void gemm_body(
    const float* __restrict__ A, const float* __restrict__ W,
    const float* __restrict__ bias, float* __restrict__ C,
    int N, int mode, int do_gelu, int round_out)
{
    __shared__ float shA[2][128 * GASTR];
    __shared__ float shW[2][32 * GWSTR];

    const int tid = threadIdx.x, lane = tid & 31, wid = tid >> 5;
    const int warpM = wid & 3, warpN = wid >> 2;
    const int bm = blockIdx.y * 128, bn = blockIdx.x * 128;
    const int lr = lane >> 2, lc = lane & 3;
    const int K = HH;

    const uint32_t sAaddr = (uint32_t)__cvta_generic_to_shared(&shA[0][0]);
    const uint32_t sWaddr = (uint32_t)__cvta_generic_to_shared(&shW[0][0]);

    const int ar = tid >> 3, ac = (tid & 7) * 4;
    const int wr = tid >> 5, wc = (tid & 31) * 4;

    auto loadA = [&](int buf, int kt) {
        #pragma unroll
        for (int i = 0; i < 4; i++) {
            int r = ar + 32 * i;
            cpa16(sAaddr + (uint32_t)(buf * 128 * GASTR + r * GASTR + ac) * 4,
                  &A[(size_t)(bm + r) * K + kt + ac]);
        }
    };
    auto loadW = [&](int buf, int kt) {
        #pragma unroll
        for (int i = 0; i < 4; i++) {
            int r = wr + 8 * i;
            cpa16(sWaddr + (uint32_t)(buf * 32 * GWSTR + r * GWSTR + wc) * 4,
                  &W[(size_t)(kt + r) * N + bn + wc]);
        }
    };

    float acc[2][8][4];
    #pragma unroll
    for (int i = 0; i < 2; i++)
        #pragma unroll
        for (int j = 0; j < 8; j++)
            #pragma unroll
            for (int k = 0; k < 4; k++) acc[i][j][k] = 0.0f;

    const int nk = K / 32;
    loadA(0, 0); loadW(0, 0); CP_COMMIT();
    loadA(1, 32); loadW(1, 32); CP_COMMIT();

    for (int kt = 0; kt < nk; kt++) {
        if (kt + 1 < nk) { CP_WAIT(1); } else { CP_WAIT(0); }
        __syncthreads();
        const int buf = kt & 1;
        const uint32_t* a_b = (const uint32_t*)&shA[buf][warpM * 32 * GASTR];
        const uint32_t* b_b = (const uint32_t*)&shW[buf][warpN * 64];
        #pragma unroll
        for (int ks = 0; ks < 4; ks++) {
            const int k = ks * 8;
            uint32_t af[2][4];
            #pragma unroll
            for (int tm = 0; tm < 2; tm++) {
                const uint32_t* p = a_b + (tm * 16 + lr) * GASTR + k + lc;
                af[tm][0] = p[0];
                af[tm][1] = p[8 * GASTR];
                af[tm][2] = p[4];
                af[tm][3] = p[8 * GASTR + 4];
            }
            #pragma unroll
            for (int tn = 0; tn < 8; tn++) {
                const uint32_t* p = b_b + (k + lc) * GWSTR + tn * 8 + lr;
                uint32_t bf[2] = { p[0], p[4 * GWSTR] };
                mma8(acc[0][tn], af[0], bf);
                mma8(acc[1][tn], af[1], bf);
            }
        }
        __syncthreads();
        if (kt + 2 < nk) { loadA(buf, (kt + 2) * 32); loadW(buf, (kt + 2) * 32); CP_COMMIT(); }
    }

    #pragma unroll
    for (int tm = 0; tm < 2; tm++)
        #pragma unroll
        for (int tn = 0; tn < 8; tn++)
            #pragma unroll
            for (int i = 0; i < 4; i++) {
                int m = bm + warpM * 32 + tm * 16 + lr + ((i >= 2) ? 8 : 0);
                int n = bn + warpN * 64 + tn * 8 + lc * 2 + (i & 1);
                float v = acc[tm][tn][i] + bias[n];
                if (do_gelu) v = 0.5f * v * (1.0f + erff(v * 0.70710678118654752f));
                if (round_out) v = __uint_as_float(f2tf(v));
                if (mode == 0) {
                    C[(size_t)m * N + n] = v;
                } else {
                    int b = m / SEQ, s = m - b * SEQ;
                    int h = n >> 6, d = n & 63;
                    if (mode == 1) C[(((size_t)b * NH + h) * SEQ + s) * HD + d] = v;
                    else           C[(((size_t)b * NH + h) * HD + d) * SEQ + s] = v;
                }
            }
}

__global__ __launch_bounds__(256, 2) void mega_qkvd(
    const float* __restrict__ q, const float* __restrict__ k, const float* __restrict__ v,
    const float* __restrict__ Wq, const float* __restrict__ bq,
    const float* __restrict__ Wk, const float* __restrict__ bk,
    const float* __restrict__ Wv, const float* __restrict__ bv,
    const float* __restrict__ W1, const float* __restrict__ b1,
    float* pQ, float* pKT, float* pV, float* pHid)
{
    const int z = blockIdx.z;
    const float *A, *W, *bias; float* C; int N, mode, gelu, ro;
    if      (z == 0) { A = q; W = Wq; bias = bq; C = pQ;   N = HH;    mode = 1; gelu = 0; ro = 1; }
    else if (z == 1) { A = k; W = Wk; bias = bk; C = pKT;  N = HH;    mode = 2; gelu = 0; ro = 1; }
    else if (z == 2) { A = v; W = Wv; bias = bv; C = pV;   N = HH;    mode = 1; gelu = 0; ro = 1; }
    else             { A = q; W = W1; bias = b1; C = pHid; N = HHALF; mode = 0; gelu = 1; ro = 0; }
    if (blockIdx.x * 128 >= N) return;
    gemm_body(A, W, bias, C, N, mode, gelu, ro);
}

__global__ __launch_bounds__(256, 2) void gemm_fo(
    const float* __restrict__ A, const float* __restrict__ W,
    const float* __restrict__ bias, float* __restrict__ C)
{
    gemm_body(A, W, bias, C, HH, 0, 0, 0);
}

// ---------------- ds2 ----------------
__global__ __launch_bounds__(512) void ds2_kernel(
    const float* __restrict__ hid, const float* __restrict__ W,
    const float* __restrict__ bias, float* __restrict__ out)
{
    __shared__ float sW[HHALF * NH];
    __shared__ float sH[16][HHALF];
    const int tid = threadIdx.x;
    const int row0 = blockIdx.x * 16;

    for (int i = tid; i < HHALF * NH; i += 512) sW[i] = W[i];
    for (int i = tid; i < 16 * HHALF; i += 512) {
        int r = i >> 9, c = i & (HHALF - 1);
        sH[r][c] = hid[(size_t)(row0 + r) * HHALF + c];
    }
    __syncthreads();

    const int r = tid >> 5, rem = tid & 31, n = rem >> 1, kh = rem & 1;
    float acc = 0.0f;
    const float* hrow = sH[r] + kh * 256;
    const float* wp = sW + kh * 256 * NH + n;
    #pragma unroll 8
    for (int k = 0; k < 256; k++) acc += hrow[k] * wp[k * NH];
    acc += __shfl_xor_sync(~0u, acc, 1);
    if (kh == 0) out[(size_t)(row0 + r) * NH + n] = 0.3f * (acc + bias[n]);
}

// ---------------- stage 1: scores + softmax -> normalized tf32 P in gmem ----------------
#define SSTR  2052
#define KTSTR 136
#define SCL   (0.125f * LOG2E)
__global__ __launch_bounds__(512, 1) void attn_score(
    const float* __restrict__ gQ, const float* __restrict__ gKT,
    const float* __restrict__ dirw, float* __restrict__ gP)
{
    extern __shared__ float sm[];
    float* sS = sm;                    // 16*2052
    float* sQ = sm + 16 * SSTR;        // 1088 (Q tile; later reductions)
    float* sK = sQ + 1088;             // 2 * 64*136
    float* sPart   = sQ;               // 256
    float* sRowMax = sQ + 256;         // 16
    float* sInv    = sQ + 288;         // 16

    const int tid = threadIdx.x, lane = tid & 31, wid = tid >> 5;  // 16 warps
    const int lr = lane >> 2, lc = lane & 3;
    const int q0 = blockIdx.x * 16;
    const int h = blockIdx.y, b = blockIdx.z;
    const size_t head = ((size_t)b * NH + h) * SEQ * HD;

    const uint32_t sQaddr = (uint32_t)__cvta_generic_to_shared(sQ);
    const uint32_t sKaddr = (uint32_t)__cvta_generic_to_shared(sK);

    auto loadKT = [&](int buf, int k0) {   // 64 x 128 (d-major)
        #pragma unroll
        for (int i = 0; i < 4; i++) {
            int idx = tid + 512 * i;
            int d = idx >> 5, c = (idx & 31) * 4;
            cpa16(sKaddr + (uint32_t)(buf * 64 * KTSTR + d * KTSTR + c) * 4,
                  &gKT[head + (size_t)d * SEQ + k0 + c]);
        }
    };

    if (tid < 256) {
        int r = tid >> 4, c = (tid & 15) * 4;
        cpa16(sQaddr + (uint32_t)(r * 68 + c) * 4, &gQ[head + (size_t)(q0 + r) * HD + c]);
    }
    CP_COMMIT();
    loadKT(0, 0); CP_COMMIT();
    loadKT(1, 128); CP_COMMIT();
    CP_WAIT(2); __syncthreads();

    uint32_t afr[8][4];
    {
        const uint32_t* sQu = (const uint32_t*)sQ;
        #pragma unroll
        for (int ks = 0; ks < 8; ks++) {
            int base = lr * 68 + ks * 8 + lc;
            afr[ks][0] = sQu[base];
            afr[ks][1] = sQu[base + 8 * 68];
            afr[ks][2] = sQu[base + 4];
            afr[ks][3] = sQu[base + 8 * 68 + 4];
        }
    }
    const float bA2 = dirw[((size_t)b * SEQ + q0 + lr) * NH + h] * LOG2E;
    const float bB2 = dirw[((size_t)b * SEQ + q0 + lr + 8) * NH + h] * LOG2E;

    float mA = -1e30f, mB = -1e30f;

    for (int t = 0; t < 16; t++) {
        if (t < 15) { CP_WAIT(1); } else { CP_WAIT(0); }
        __syncthreads();
        const int buf = t & 1;
        const uint32_t* kbu = (const uint32_t*)(sK + buf * 64 * KTSTR) + wid * 8 + lr;
        float acc[4] = {0, 0, 0, 0};
        #pragma unroll
        for (int ks = 0; ks < 8; ks++) {
            const uint32_t* p = kbu + (ks * 8 + lc) * KTSTR;
            uint32_t bf[2] = { p[0], p[4 * KTSTR] };
            mma8(acc, afr[ks], bf);
        }
        float v0 = acc[0] * SCL + bA2, v1 = acc[1] * SCL + bA2;
        float v2 = acc[2] * SCL + bB2, v3 = acc[3] * SCL + bB2;
        mA = fmaxf(mA, fmaxf(v0, v1));
        mB = fmaxf(mB, fmaxf(v2, v3));
        float* s0 = sS + lr * SSTR + t * 128 + wid * 8 + 2 * lc;
        *(float2*)s0 = make_float2(v0, v1);
        *(float2*)(s0 + 8 * SSTR) = make_float2(v2, v3);
        __syncthreads();
        if (t + 2 < 16) { loadKT(buf, (t + 2) * 128); CP_COMMIT(); }
    }

    mA = fmaxf(mA, __shfl_xor_sync(~0u, mA, 1));
    mA = fmaxf(mA, __shfl_xor_sync(~0u, mA, 2));
    mB = fmaxf(mB, __shfl_xor_sync(~0u, mB, 1));
    mB = fmaxf(mB, __shfl_xor_sync(~0u, mB, 2));
    if (lc == 0) { sPart[wid * 16 + lr] = mA; sPart[wid * 16 + lr + 8] = mB; }
    __syncthreads();
    if (tid < 16) {
        float m = sPart[tid];
        #pragma unroll
        for (int w = 1; w < 16; w++) m = fmaxf(m, sPart[w * 16 + tid]);
        sRowMax[tid] = m;
    }
    __syncthreads();

    // exp + sum (tf32-rounded exp kept in smem)
    {
        const float m = sRowMax[wid];
        float4* row4 = (float4*)(sS + (size_t)wid * SSTR);
        float sum = 0.0f;
        for (int i = lane; i < SEQ / 4; i += 32) {
            float4 v = row4[i];
            v.x = __uint_as_float(f2tf(ex2f(v.x - m)));
            v.y = __uint_as_float(f2tf(ex2f(v.y - m)));
            v.z = __uint_as_float(f2tf(ex2f(v.z - m)));
            v.w = __uint_as_float(f2tf(ex2f(v.w - m)));
            sum += v.x + v.y + v.z + v.w;
            row4[i] = v;
        }
        #pragma unroll
        for (int o = 16; o; o >>= 1) sum += __shfl_xor_sync(~0u, sum, o);
        if (lane == 0) sInv[wid] = 1.0f / sum;
    }
    __syncthreads();

    // normalize (tf32-round) + write P to gmem
    {
        const float inv = sInv[wid];
        const float4* row4 = (const float4*)(sS + (size_t)wid * SSTR);
        float4* dst = (float4*)(gP + (((size_t)b * NH + h) * SEQ + (q0 + wid)) * SEQ);
        for (int i = lane; i < SEQ / 4; i += 32) {
            float4 v = row4[i];
            v.x = __uint_as_float(f2tf(v.x * inv));
            v.y = __uint_as_float(f2tf(v.y * inv));
            v.z = __uint_as_float(f2tf(v.z * inv));
            v.w = __uint_as_float(f2tf(v.w * inv));
            dst[i] = v;
        }
    }
}

// ---------------- stage 2: ctx = P @ V (128x64 tiles, K=2048) ----------------
#define PASTR 36
#define VSTR2 72
__global__ __launch_bounds__(256) void attn_av(
    const float* __restrict__ gP, const float* __restrict__ gV,
    float* __restrict__ gCtx)
{
    extern __shared__ float sm[];
    float* sP = sm;                 // 2 * 128*36
    float* sV = sm + 2 * 128 * PASTR;   // 2 * 32*72

    const int tid = threadIdx.x, lane = tid & 31, wid = tid >> 5;
    const int warpM = wid & 3, warpN = wid >> 2;   // 4 x 2
    const int lr = lane >> 2, lc = lane & 3;
    const int q0 = blockIdx.x * 128;
    const int h = blockIdx.y, b = blockIdx.z;
    const size_t prow0 = (((size_t)b * NH + h) * SEQ + q0) * SEQ;
    const size_t head  = ((size_t)b * NH + h) * SEQ * HD;

    const uint32_t sPaddr = (uint32_t)__cvta_generic_to_shared(sP);
    const uint32_t sVaddr = (uint32_t)__cvta_generic_to_shared(sV);

    auto loadP = [&](int buf, int kt) {   // 128 rows x 32 cols
        #pragma unroll
        for (int i = 0; i < 4; i++) {
            int idx = tid + 256 * i;
            int r = idx >> 3, c = (idx & 7) * 4;
            cpa16(sPaddr + (uint32_t)(buf * 128 * PASTR + r * PASTR + c) * 4,
                  &gP[prow0 + (size_t)r * SEQ + kt + c]);
        }
    };
    auto loadV = [&](int buf, int kt) {   // 32 keys x 64 dims
        #pragma unroll
        for (int i = 0; i < 2; i++) {
            int idx = tid + 256 * i;
            int r = idx >> 4, c = (idx & 15) * 4;
            cpa16(sVaddr + (uint32_t)(buf * 32 * VSTR2 + r * VSTR2 + c) * 4,
                  &gV[head + (size_t)(kt + r) * HD + c]);
        }
    };

    float acc[2][4][4];
    #pragma unroll
    for (int i = 0; i < 2; i++)
        #pragma unroll
        for (int j = 0; j < 4; j++)
            #pragma unroll
            for (int k = 0; k < 4; k++) acc[i][j][k] = 0.0f;

    loadP(0, 0); loadV(0, 0); CP_COMMIT();
    loadP(1, 32); loadV(1, 32); CP_COMMIT();

    const int nk = SEQ / 32;   // 64
    for (int kt = 0; kt < nk; kt++) {
        if (kt + 1 < nk) { CP_WAIT(1); } else { CP_WAIT(0); }
        __syncthreads();
        const int buf = kt & 1;
        const uint32_t* a_b = (const uint32_t*)(sP + buf * 128 * PASTR) + warpM * 32 * PASTR;
        const uint32_t* b_b = (const uint32_t*)(sV + buf * 32 * VSTR2) + warpN * 32;
        #pragma unroll
        for (int ks = 0; ks < 4; ks++) {
            const int k = ks * 8;
            uint32_t af[2][4];
            #pragma unroll
            for (int tm = 0; tm < 2; tm++) {
                const uint32_t* p = a_b + (tm * 16 + lr) * PASTR + k + lc;
                af[tm][0] = p[0];
                af[tm][1] = p[8 * PASTR];
                af[tm][2] = p[4];
                af[tm][3] = p[8 * PASTR + 4];
            }
            #pragma unroll
            for (int tn = 0; tn < 4; tn++) {
                const uint32_t* p = b_b + (k + lc) * VSTR2 + tn * 8 + lr;
                uint32_t bf[2] = { p[0], p[4 * VSTR2] };
                mma8(acc[0][tn], af[0], bf);
                mma8(acc[1][tn], af[1], bf);
            }
        }
        __syncthreads();
        if (kt + 2 < nk) { loadP(buf, (kt + 2) * 32); loadV(buf, (kt + 2) * 32); CP_COMMIT(); }
    }

    #pragma unroll
    for (int tm = 0; tm < 2; tm++)
        #pragma unroll
        for (int tn = 0; tn < 4; tn++)
            #pragma unroll
            for (int i = 0; i < 4; i++) {
                int s = q0 + warpM * 32 + tm * 16 + lr + ((i >= 2) ? 8 : 0);
                int d = warpN * 32 + tn * 8 + lc * 2 + (i & 1);
                gCtx[(((size_t)b * SEQ + s) * NH + h) * HD + d] =
                    __uint_as_float(f2tf(acc[tm][tn][i]));
            }
}

// ---------------- host launcher ----------------
extern "C" void kernel_launch(void* const* d_in, const int* in_sizes, int n_in,
                              void* d_out, int out_size)
{
    const float* query  = (const float*)d_in[0];
    const float* key_in = (const float*)d_in[1];
    const float* value  = (const float*)d_in[2];
    const float* Wq_w = (const float*)d_in[4];
    const float* Wq_b = (const float*)d_in[5];
    const float* Wk_w = (const float*)d_in[6];
    const float* Wk_b = (const float*)d_in[7];
    const float* Wv_w = (const float*)d_in[8];
    const float* Wv_b = (const float*)d_in[9];
    const float* ds1_w = (const float*)d_in[10];
    const float* ds1_b = (const float*)d_in[11];
    const float* ds2_w = (const float*)d_in[12];
    const float* ds2_b = (const float*)d_in[13];
    const float* fo_w  = (const float*)d_in[14];
    const float* fo_b  = (const float*)d_in[15];

    float *pQ, *pKT, *pV, *pCtx, *pHid, *pDirw, *pP;
    float *prq, *prk, *prv, *prwq, *prwk, *prwv, *prwo, *prw1;
    cudaGetSymbolAddress((void**)&pQ,    g_Q);
    cudaGetSymbolAddress((void**)&pKT,   g_KT);
    cudaGetSymbolAddress((void**)&pV,    g_V);
    cudaGetSymbolAddress((void**)&pCtx,  g_ctx);
    cudaGetSymbolAddress((void**)&pHid,  g_hid);
    cudaGetSymbolAddress((void**)&pDirw, g_dirw);
    cudaGetSymbolAddress((void**)&pP,    g_P);
    cudaGetSymbolAddress((void**)&prq,   g_rq);
    cudaGetSymbolAddress((void**)&prk,   g_rk);
    cudaGetSymbolAddress((void**)&prv,   g_rv);
    cudaGetSymbolAddress((void**)&prwq,  g_rwq);
    cudaGetSymbolAddress((void**)&prwk,  g_rwk);
    cudaGetSymbolAddress((void**)&prwv,  g_rwv);
    cudaGetSymbolAddress((void**)&prwo,  g_rwo);
    cudaGetSymbolAddress((void**)&prw1,  g_rw1);

    // 0) tf32-preround inputs + weights (removes all CVTs from GEMM mainloops)
    preround8<<<1024, 256>>>(
        query,  prq,  MM * HH,  key_in, prk,  MM * HH,
        value,  prv,  MM * HH,  Wq_w,   prwq, HH * HH,
        Wk_w,   prwk, HH * HH,  Wv_w,   prwv, HH * HH,
        fo_w,   prwo, HH * HH,  ds1_w,  prw1, HH * HHALF);

    // 1) QKV + ds1
    mega_qkvd<<<dim3(HH / 128, MM / 128, 4), 256>>>(
        prq, prk, prv, prwq, Wq_b, prwk, Wk_b, prwv, Wv_b,
        prw1, ds1_b, pQ, pKT, pV, pHid);

    ds2_kernel<<<MM / 16, 512>>>(pHid, ds2_w, ds2_b, pDirw);

    // 2) attention
    const size_t outElems  = (size_t)MM * HH;
    const size_t attnElems = (size_t)BB * NH * SEQ * (size_t)SEQ;
    int writeAttn = ((size_t)out_size >= outElems + attnElems) ? 1 : 0;
    float* gP = writeAttn ? ((float*)d_out + outElems) : pP;

    size_t smem1 = (size_t)(16 * SSTR + 1088 + 2 * 64 * KTSTR) * sizeof(float); // 205312
    cudaFuncSetAttribute(attn_score, cudaFuncAttributeMaxDynamicSharedMemorySize, (int)smem1);
    attn_score<<<dim3(SEQ / 16, NH, BB), 512, smem1>>>(pQ, pKT, pDirw, gP);

    size_t smem2 = (size_t)(2 * 128 * PASTR + 2 * 32 * VSTR2) * sizeof(float); // 55296
    cudaFuncSetAttribute(attn_av, cudaFuncAttributeMaxDynamicSharedMemorySize, (int)smem2);
    attn_av<<<dim3(SEQ / 128, NH, BB), 256, smem2>>>(gP, pV, pCtx);

    // 3) output projection
    gemm_fo<<<dim3(HH / 128, MM / 128), 256>>>(pCtx, prwo, fo_b, (float*)d_out);
}

// round 6
// speedup vs baseline: 5.0403x; 1.0258x over previous
#include <cuda_runtime.h>
#include <math.h>
#include <stdint.h>

// ---------------- problem constants ----------------
#define BB 2
#define SEQ 2048
#define HH 1024
#define NH 16
#define HD 64
#define MM (BB*SEQ)          // 4096
#define LOG2E 1.4426950408889634f

// ---------------- scratch ----------------
__device__ float g_Q  [(size_t)MM*HH];   // (b,h,s,d)  tf32-rounded
__device__ float g_KT [(size_t)MM*HH];   // (b,h,d,s)  tf32-rounded
__device__ float g_V  [(size_t)MM*HH];   // (b,h,s,d)  tf32-rounded
__device__ float g_ctx[(size_t)MM*HH];   // (b,s,h,d)  tf32-rounded
// pre-rounded (tf32) copies of inputs & weights
__device__ float g_rq [(size_t)MM*HH];
__device__ float g_rk [(size_t)MM*HH];
__device__ float g_rv [(size_t)MM*HH];
__device__ float g_rwq[(size_t)HH*HH];
__device__ float g_rwk[(size_t)HH*HH];
__device__ float g_rwv[(size_t)HH*HH];
__device__ float g_rwo[(size_t)HH*HH];
// fallback P storage when attention is not part of d_out
__device__ float g_P  [(size_t)BB*NH*SEQ*(size_t)SEQ];

// ---------------- helpers ----------------
__device__ __forceinline__ uint32_t f2tf(float x) {
    uint32_t r; asm("cvt.rna.tf32.f32 %0, %1;" : "=r"(r) : "f"(x)); return r;
}
__device__ __forceinline__ float ex2f(float x) {
    float y; asm("ex2.approx.ftz.f32 %0, %1;" : "=f"(y) : "f"(x)); return y;
}
__device__ __forceinline__ void mma8(float* c, const uint32_t* a, const uint32_t* b) {
    asm volatile(
        "mma.sync.aligned.m16n8k8.row.col.f32.tf32.tf32.f32 "
        "{%0,%1,%2,%3}, {%4,%5,%6,%7}, {%8,%9}, {%0,%1,%2,%3};"
        : "+f"(c[0]), "+f"(c[1]), "+f"(c[2]), "+f"(c[3])
        : "r"(a[0]), "r"(a[1]), "r"(a[2]), "r"(a[3]), "r"(b[0]), "r"(b[1]));
}
__device__ __forceinline__ void cpa16(uint32_t dst, const void* src) {
    asm volatile("cp.async.cg.shared.global [%0], [%1], 16;" :: "r"(dst), "l"(src));
}
#define CP_COMMIT() asm volatile("cp.async.commit_group;")
#define CP_WAIT(N)  asm volatile("cp.async.wait_group %0;" :: "n"(N))

// ---------------- preround: tf32-round inputs + weights ----------------
__global__ __launch_bounds__(256) void preround7(
    const float* s0, float* d0, int n0, const float* s1, float* d1, int n1,
    const float* s2, float* d2, int n2, const float* s3, float* d3, int n3,
    const float* s4, float* d4, int n4, const float* s5, float* d5, int n5,
    const float* s6, float* d6, int n6)
{
    const float* srcs[7] = {s0,s1,s2,s3,s4,s5,s6};
    float*       dsts[7] = {d0,d1,d2,d3,d4,d5,d6};
    int          ns[7]   = {n0,n1,n2,n3,n4,n5,n6};
    const int stride = gridDim.x * blockDim.x;
    const int t0 = blockIdx.x * blockDim.x + threadIdx.x;
    for (int t = 0; t < 7; t++) {
        const float4* src = (const float4*)srcs[t];
        float4* dst = (float4*)dsts[t];
        const int nq = ns[t] >> 2;
        for (int i = t0; i < nq; i += stride) {
            float4 v = src[i];
            v.x = __uint_as_float(f2tf(v.x)); v.y = __uint_as_float(f2tf(v.y));
            v.z = __uint_as_float(f2tf(v.z)); v.w = __uint_as_float(f2tf(v.w));
            dst[i] = v;
        }
    }
}

// ---------------- shared TC GEMM body (raw tf32 operands, no CVT) ----------------
#define GASTR 36
#define GWSTR 136
__device__ __forceinline__ void gemm_body(
    const float* __restrict__ A, const float* __restrict__ W,
    const float* __restrict__ bias, float* __restrict__ C,
    int N, int mode, int round_out)
{
    __shared__ float shA[2][128 * GASTR];
    __shared__ float shW[2][32 * GWSTR];

    const int tid = threadIdx.x, lane = tid & 31, wid = tid >> 5;
    const int warpM = wid & 3, warpN = wid >> 2;
    const int bm = blockIdx.y * 128, bn = blockIdx.x * 128;
    const int lr = lane >> 2, lc = lane & 3;
    const int K = HH;

    const uint32_t sAaddr = (uint32_t)__cvta_generic_to_shared(&shA[0][0]);
    const uint32_t sWaddr = (uint32_t)__cvta_generic_to_shared(&shW[0][0]);

    const int ar = tid >> 3, ac = (tid & 7) * 4;
    const int wr = tid >> 5, wc = (tid & 31) * 4;

    auto loadA = [&](int buf, int kt) {
        #pragma unroll
        for (int i = 0; i < 4; i++) {
            int r = ar + 32 * i;
            cpa16(sAaddr + (uint32_t)(buf * 128 * GASTR + r * GASTR + ac) * 4,
                  &A[(size_t)(bm + r) * K + kt + ac]);
        }
    };
    auto loadW = [&](int buf, int kt) {
        #pragma unroll
        for (int i = 0; i < 4; i++) {
            int r = wr + 8 * i;
            cpa16(sWaddr + (uint32_t)(buf * 32 * GWSTR + r * GWSTR + wc) * 4,
                  &W[(size_t)(kt + r) * N + bn + wc]);
        }
    };

    float acc[2][8][4];
    #pragma unroll
    for (int i = 0; i < 2; i++)
        #pragma unroll
        for (int j = 0; j < 8; j++)
            #pragma unroll
            for (int k = 0; k < 4; k++) acc[i][j][k] = 0.0f;

    const int nk = K / 32;
    loadA(0, 0); loadW(0, 0); CP_COMMIT();
    loadA(1, 32); loadW(1, 32); CP_COMMIT();

    for (int kt = 0; kt < nk; kt++) {
        if (kt + 1 < nk) { CP_WAIT(1); } else { CP_WAIT(0); }
        __syncthreads();
        const int buf = kt & 1;
        const uint32_t* a_b = (const uint32_t*)&shA[buf][warpM * 32 * GASTR];
        const uint32_t* b_b = (const uint32_t*)&shW[buf][warpN * 64];
        #pragma unroll
        for (int ks = 0; ks < 4; ks++) {
            const int k = ks * 8;
            uint32_t af[2][4];
            #pragma unroll
            for (int tm = 0; tm < 2; tm++) {
                const uint32_t* p = a_b + (tm * 16 + lr) * GASTR + k + lc;
                af[tm][0] = p[0];
                af[tm][1] = p[8 * GASTR];
                af[tm][2] = p[4];
                af[tm][3] = p[8 * GASTR + 4];
            }
            #pragma unroll
            for (int tn = 0; tn < 8; tn++) {
                const uint32_t* p = b_b + (k + lc) * GWSTR + tn * 8 + lr;
                uint32_t bf[2] = { p[0], p[4 * GWSTR] };
                mma8(acc[0][tn], af[0], bf);
                mma8(acc[1][tn], af[1], bf);
            }
        }
        __syncthreads();
        if (kt + 2 < nk) { loadA(buf, (kt + 2) * 32); loadW(buf, (kt + 2) * 32); CP_COMMIT(); }
    }

    #pragma unroll
    for (int tm = 0; tm < 2; tm++)
        #pragma unroll
        for (int tn = 0; tn < 8; tn++)
            #pragma unroll
            for (int i = 0; i < 4; i++) {
                int m = bm + warpM * 32 + tm * 16 + lr + ((i >= 2) ? 8 : 0);
                int n = bn + warpN * 64 + tn * 8 + lc * 2 + (i & 1);
                float v = acc[tm][tn][i] + bias[n];
                if (round_out) v = __uint_as_float(f2tf(v));
                if (mode == 0) {
                    C[(size_t)m * N + n] = v;
                } else {
                    int b = m / SEQ, s = m - b * SEQ;
                    int h = n >> 6, d = n & 63;
                    if (mode == 1) C[(((size_t)b * NH + h) * SEQ + s) * HD + d] = v;
                    else           C[(((size_t)b * NH + h) * HD + d) * SEQ + s] = v;
                }
            }
}

__global__ __launch_bounds__(256, 2) void mega_qkv(
    const float* __restrict__ q, const float* __restrict__ k, const float* __restrict__ v,
    const float* __restrict__ Wq, const float* __restrict__ bq,
    const float* __restrict__ Wk, const float* __restrict__ bk,
    const float* __restrict__ Wv, const float* __restrict__ bv,
    float* pQ, float* pKT, float* pV)
{
    const int z = blockIdx.z;
    const float *A, *W, *bias; float* C; int mode;
    if      (z == 0) { A = q; W = Wq; bias = bq; C = pQ;  mode = 1; }
    else if (z == 1) { A = k; W = Wk; bias = bk; C = pKT; mode = 2; }
    else             { A = v; W = Wv; bias = bv; C = pV;  mode = 1; }
    gemm_body(A, W, bias, C, HH, mode, 1);
}

__global__ __launch_bounds__(256, 2) void gemm_fo(
    const float* __restrict__ A, const float* __restrict__ W,
    const float* __restrict__ bias, float* __restrict__ C)
{
    gemm_body(A, W, bias, C, HH, 0, 0);
}

// ---------------- stage 1: scores (M=128) + softmax, in-place in gP ----------------
#define QSTR 68
#define KSTR 72
#define SCL  (0.125f * LOG2E)
__global__ __launch_bounds__(256, 2) void attn_score_big(
    const float* __restrict__ gQ, const float* __restrict__ gKT,
    float* __restrict__ gP)
{
    extern __shared__ float sm[];
    float* sQ   = sm;                         // 128*68 = 8704
    float* sK   = sQ + 128 * QSTR;            // 2 * 64*72 = 9216
    float* sMax = sK + 2 * 64 * KSTR;         // 256
    float* sM   = sMax + 256;                 // 128

    const int tid = threadIdx.x, lane = tid & 31, wid = tid >> 5;
    const int warpM = wid & 3, warpN = wid >> 2;   // 4 x 2
    const int lr = lane >> 2, lc = lane & 3;
    const int q0 = blockIdx.x * 128;
    const int h = blockIdx.y, b = blockIdx.z;
    const size_t head  = ((size_t)b * NH + h) * SEQ * HD;
    const size_t prow0 = (((size_t)b * NH + h) * SEQ + q0) * SEQ;

    const uint32_t sQa = (uint32_t)__cvta_generic_to_shared(sQ);
    const uint32_t sKa = (uint32_t)__cvta_generic_to_shared(sK);

    // Q tile 128x64 (stride 68)
    #pragma unroll
    for (int i = 0; i < 8; i++) {
        int idx = tid + 256 * i;
        int r = idx >> 4, c = (idx & 15) * 4;
        cpa16(sQa + (uint32_t)(r * QSTR + c) * 4, &gQ[head + (size_t)(q0 + r) * HD + c]);
    }
    CP_COMMIT();

    auto loadK = [&](int buf, int k0) {   // 64 d x 64 keys (stride 72)
        #pragma unroll
        for (int i = 0; i < 4; i++) {
            int idx = tid + 256 * i;
            int d = idx >> 4, c = (idx & 15) * 4;
            cpa16(sKa + (uint32_t)(buf * 64 * KSTR + d * KSTR + c) * 4,
                  &gKT[head + (size_t)d * SEQ + k0 + c]);
        }
    };
    loadK(0, 0); CP_COMMIT();
    loadK(1, 64); CP_COMMIT();
    CP_WAIT(2); __syncthreads();   // Q resident

    // hoist Q fragments (raw tf32 bits, constant over all key tiles)
    uint32_t afr[2][8][4];
    {
        const uint32_t* sQu = (const uint32_t*)sQ;
        #pragma unroll
        for (int tm = 0; tm < 2; tm++)
            #pragma unroll
            for (int ks = 0; ks < 8; ks++) {
                int base = (warpM * 32 + tm * 16 + lr) * QSTR + ks * 8 + lc;
                afr[tm][ks][0] = sQu[base];
                afr[tm][ks][1] = sQu[base + 8 * QSTR];
                afr[tm][ks][2] = sQu[base + 4];
                afr[tm][ks][3] = sQu[base + 8 * QSTR + 4];
            }
    }

    float mrun[2][2] = {{-1e30f, -1e30f}, {-1e30f, -1e30f}};

    // ---- mainloop: 32 key tiles of 64 ----
    for (int t = 0; t < 32; t++) {
        if (t < 31) { CP_WAIT(1); } else { CP_WAIT(0); }
        __syncthreads();
        const int buf = t & 1;
        const uint32_t* kb = (const uint32_t*)(sK + buf * 64 * KSTR) + warpN * 32 + lr;

        float acc[2][4][4];
        #pragma unroll
        for (int i = 0; i < 2; i++)
            #pragma unroll
            for (int j = 0; j < 4; j++)
                #pragma unroll
                for (int k = 0; k < 4; k++) acc[i][j][k] = 0.0f;

        #pragma unroll
        for (int ks = 0; ks < 8; ks++) {
            #pragma unroll
            for (int tn = 0; tn < 4; tn++) {
                const uint32_t* p = kb + (ks * 8 + lc) * KSTR + tn * 8;
                uint32_t bf[2] = { p[0], p[4 * KSTR] };
                mma8(acc[0][tn], afr[0][ks], bf);
                mma8(acc[1][tn], afr[1][ks], bf);
            }
        }
        __syncthreads();   // done reading buf
        if (t + 2 < 32) { loadK(buf, (t + 2) * 64); CP_COMMIT(); }

        // scale, track row max, spill raw (log2-domain) scores
        #pragma unroll
        for (int tm = 0; tm < 2; tm++) {
            #pragma unroll
            for (int j = 0; j < 2; j++) {
                float v[8];
                #pragma unroll
                for (int tn = 0; tn < 4; tn++) {
                    v[2 * tn]     = acc[tm][tn][2 * j]     * SCL;
                    v[2 * tn + 1] = acc[tm][tn][2 * j + 1] * SCL;
                }
                float lm = v[0];
                #pragma unroll
                for (int i = 1; i < 8; i++) lm = fmaxf(lm, v[i]);
                lm = fmaxf(lm, __shfl_xor_sync(~0u, lm, 1));
                lm = fmaxf(lm, __shfl_xor_sync(~0u, lm, 2));
                mrun[tm][j] = fmaxf(mrun[tm][j], lm);

                int row = warpM * 32 + tm * 16 + lr + 8 * j;
                float* dst = gP + prow0 + (size_t)row * SEQ + t * 64 + warpN * 32 + lc * 2;
                #pragma unroll
                for (int tn = 0; tn < 4; tn++)
                    *(float2*)(dst + tn * 8) = make_float2(v[2 * tn], v[2 * tn + 1]);
            }
        }
    }

    // ---- combine warpN-partial row maxes ----
    if (lc == 0) {
        #pragma unroll
        for (int tm = 0; tm < 2; tm++)
            #pragma unroll
            for (int j = 0; j < 2; j++)
                sMax[warpN * 128 + warpM * 32 + tm * 16 + lr + 8 * j] = mrun[tm][j];
    }
    __syncthreads();
    if (tid < 128) sM[tid] = fmaxf(sMax[tid], sMax[128 + tid]);
    __syncthreads();

    // ---- epilogue: per row: exp pass (write exp, accumulate sum), then scale pass ----
    #pragma unroll 1
    for (int rr = 0; rr < 16; rr++) {
        const int row = wid * 16 + rr;
        const float m = sM[row];
        float4* rp = (float4*)(gP + prow0 + (size_t)row * SEQ);
        float s = 0.0f;
        #pragma unroll 4
        for (int i = lane; i < SEQ / 4; i += 32) {
            float4 v = rp[i];
            v.x = ex2f(v.x - m); v.y = ex2f(v.y - m);
            v.z = ex2f(v.z - m); v.w = ex2f(v.w - m);
            s += v.x + v.y + v.z + v.w;
            rp[i] = v;
        }
        #pragma unroll
        for (int o = 16; o; o >>= 1) s += __shfl_xor_sync(~0u, s, o);
        const float inv = 1.0f / s;
        #pragma unroll 4
        for (int i = lane; i < SEQ / 4; i += 32) {
            float4 v = rp[i];
            v.x = __uint_as_float(f2tf(v.x * inv));
            v.y = __uint_as_float(f2tf(v.y * inv));
            v.z = __uint_as_float(f2tf(v.z * inv));
            v.w = __uint_as_float(f2tf(v.w * inv));
            rp[i] = v;
        }
    }
}

// ---------------- stage 2: ctx = P @ V (128x64 tiles, K=2048) ----------------
#define PASTR 36
#define VSTR2 72
__global__ __launch_bounds__(256) void attn_av(
    const float* __restrict__ gP, const float* __restrict__ gV,
    float* __restrict__ gCtx)
{
    extern __shared__ float sm[];
    float* sP = sm;                      // 2 * 128*36
    float* sV = sm + 2 * 128 * PASTR;    // 2 * 32*72

    const int tid = threadIdx.x, lane = tid & 31, wid = tid >> 5;
    const int warpM = wid & 3, warpN = wid >> 2;   // 4 x 2
    const int lr = lane >> 2, lc = lane & 3;
    const int q0 = blockIdx.x * 128;
    const int h = blockIdx.y, b = blockIdx.z;
    const size_t prow0 = (((size_t)b * NH + h) * SEQ + q0) * SEQ;
    const size_t head  = ((size_t)b * NH + h) * SEQ * HD;

    const uint32_t sPaddr = (uint32_t)__cvta_generic_to_shared(sP);
    const uint32_t sVaddr = (uint32_t)__cvta_generic_to_shared(sV);

    auto loadP = [&](int buf, int kt) {
        #pragma unroll
        for (int i = 0; i < 4; i++) {
            int idx = tid + 256 * i;
            int r = idx >> 3, c = (idx & 7) * 4;
            cpa16(sPaddr + (uint32_t)(buf * 128 * PASTR + r * PASTR + c) * 4,
                  &gP[prow0 + (size_t)r * SEQ + kt + c]);
        }
    };
    auto loadV = [&](int buf, int kt) {
        #pragma unroll
        for (int i = 0; i < 2; i++) {
            int idx = tid + 256 * i;
            int r = idx >> 4, c = (idx & 15) * 4;
            cpa16(sVaddr + (uint32_t)(buf * 32 * VSTR2 + r * VSTR2 + c) * 4,
                  &gV[head + (size_t)(kt + r) * HD + c]);
        }
    };

    float acc[2][4][4];
    #pragma unroll
    for (int i = 0; i < 2; i++)
        #pragma unroll
        for (int j = 0; j < 4; j++)
            #pragma unroll
            for (int k = 0; k < 4; k++) acc[i][j][k] = 0.0f;

    loadP(0, 0); loadV(0, 0); CP_COMMIT();
    loadP(1, 32); loadV(1, 32); CP_COMMIT();

    const int nk = SEQ / 32;   // 64
    for (int kt = 0; kt < nk; kt++) {
        if (kt + 1 < nk) { CP_WAIT(1); } else { CP_WAIT(0); }
        __syncthreads();
        const int buf = kt & 1;
        const uint32_t* a_b = (const uint32_t*)(sP + buf * 128 * PASTR) + warpM * 32 * PASTR;
        const uint32_t* b_b = (const uint32_t*)(sV + buf * 32 * VSTR2) + warpN * 32;
        #pragma unroll
        for (int ks = 0; ks < 4; ks++) {
            const int k = ks * 8;
            uint32_t af[2][4];
            #pragma unroll
            for (int tm = 0; tm < 2; tm++) {
                const uint32_t* p = a_b + (tm * 16 + lr) * PASTR + k + lc;
                af[tm][0] = p[0];
                af[tm][1] = p[8 * PASTR];
                af[tm][2] = p[4];
                af[tm][3] = p[8 * PASTR + 4];
            }
            #pragma unroll
            for (int tn = 0; tn < 4; tn++) {
                const uint32_t* p = b_b + (k + lc) * VSTR2 + tn * 8 + lr;
                uint32_t bf[2] = { p[0], p[4 * VSTR2] };
                mma8(acc[0][tn], af[0], bf);
                mma8(acc[1][tn], af[1], bf);
            }
        }
        __syncthreads();
        if (kt + 2 < nk) { loadP(buf, (kt + 2) * 32); loadV(buf, (kt + 2) * 32); CP_COMMIT(); }
    }

    #pragma unroll
    for (int tm = 0; tm < 2; tm++)
        #pragma unroll
        for (int tn = 0; tn < 4; tn++)
            #pragma unroll
            for (int i = 0; i < 4; i++) {
                int s = q0 + warpM * 32 + tm * 16 + lr + ((i >= 2) ? 8 : 0);
                int d = warpN * 32 + tn * 8 + lc * 2 + (i & 1);
                gCtx[(((size_t)b * SEQ + s) * NH + h) * HD + d] =
                    __uint_as_float(f2tf(acc[tm][tn][i]));
            }
}

// ---------------- host launcher ----------------
extern "C" void kernel_launch(void* const* d_in, const int* in_sizes, int n_in,
                              void* d_out, int out_size)
{
    const float* query  = (const float*)d_in[0];
    const float* key_in = (const float*)d_in[1];
    const float* value  = (const float*)d_in[2];
    // d_in[3] = direction_signal (unused by reference math)
    const float* Wq_w = (const float*)d_in[4];
    const float* Wq_b = (const float*)d_in[5];
    const float* Wk_w = (const float*)d_in[6];
    const float* Wk_b = (const float*)d_in[7];
    const float* Wv_w = (const float*)d_in[8];
    const float* Wv_b = (const float*)d_in[9];
    // ds1/ds2 (d_in[10..13]) are a per-query additive constant over keys:
    // softmax is invariant to them, so they are skipped entirely.
    const float* fo_w  = (const float*)d_in[14];
    const float* fo_b  = (const float*)d_in[15];

    float *pQ, *pKT, *pV, *pCtx, *pP;
    float *prq, *prk, *prv, *prwq, *prwk, *prwv, *prwo;
    cudaGetSymbolAddress((void**)&pQ,   g_Q);
    cudaGetSymbolAddress((void**)&pKT,  g_KT);
    cudaGetSymbolAddress((void**)&pV,   g_V);
    cudaGetSymbolAddress((void**)&pCtx, g_ctx);
    cudaGetSymbolAddress((void**)&pP,   g_P);
    cudaGetSymbolAddress((void**)&prq,  g_rq);
    cudaGetSymbolAddress((void**)&prk,  g_rk);
    cudaGetSymbolAddress((void**)&prv,  g_rv);
    cudaGetSymbolAddress((void**)&prwq, g_rwq);
    cudaGetSymbolAddress((void**)&prwk, g_rwk);
    cudaGetSymbolAddress((void**)&prwv, g_rwv);
    cudaGetSymbolAddress((void**)&prwo, g_rwo);

    // 0) tf32-preround inputs + weights
    preround7<<<1024, 256>>>(
        query,  prq,  MM * HH,  key_in, prk,  MM * HH,
        value,  prv,  MM * HH,  Wq_w,   prwq, HH * HH,
        Wk_w,   prwk, HH * HH,  Wv_w,   prwv, HH * HH,
        fo_w,   prwo, HH * HH);

    // 1) QKV projections
    mega_qkv<<<dim3(HH / 128, MM / 128, 3), 256>>>(
        prq, prk, prv, prwq, Wq_b, prwk, Wk_b, prwv, Wv_b, pQ, pKT, pV);

    // 2) attention
    const size_t outElems  = (size_t)MM * HH;
    const size_t attnElems = (size_t)BB * NH * SEQ * (size_t)SEQ;
    int writeAttn = ((size_t)out_size >= outElems + attnElems) ? 1 : 0;
    float* gP = writeAttn ? ((float*)d_out + outElems) : pP;

    size_t smem1 = (size_t)(128 * QSTR + 2 * 64 * KSTR + 256 + 128) * sizeof(float); // 73216
    cudaFuncSetAttribute(attn_score_big, cudaFuncAttributeMaxDynamicSharedMemorySize, (int)smem1);
    attn_score_big<<<dim3(SEQ / 128, NH, BB), 256, smem1>>>(pQ, pKT, gP);

    size_t smem2 = (size_t)(2 * 128 * PASTR + 2 * 32 * VSTR2) * sizeof(float); // 55296
    cudaFuncSetAttribute(attn_av, cudaFuncAttributeMaxDynamicSharedMemorySize, (int)smem2);
    attn_av<<<dim3(SEQ / 128, NH, BB), 256, smem2>>>(gP, pV, pCtx);

    // 3) output projection
    gemm_fo<<<dim3(HH / 128, MM / 128), 256>>>(pCtx, prwo, fo_b, (float*)d_out);
}